// round 2
// baseline (speedup 1.0000x reference)
#include <cuda_runtime.h>

#define T_DIM 4096
#define C_DIM 768
#define H_DIM 12
#define D_DIM 64
#define F_DIM 2304   // 3*C

// Scratch (allocation-free: __device__ globals)
__device__ float g_qkv[T_DIM * F_DIM];   // [t][f] f: 0..767 Q, 768..1535 K, 1536..2303 V
__device__ float g_y[T_DIM * C_DIM];     // attention output [t][h*64+d]

// ---------------------------------------------------------------------------
// Generic 128x128x16 SGEMM body: C = A[MxK] @ B[KxN] + bias, all row-major,
// M % 128 == 0, N % 128 == 0, K % 16 == 0 (true for both GEMMs here).
// 256 threads, 8x8 per-thread microtile.
// ---------------------------------------------------------------------------
__device__ __forceinline__ void sgemm_body(const float* __restrict__ A,
                                           const float* __restrict__ Bm,
                                           const float* __restrict__ bias,
                                           float* __restrict__ Cc,
                                           int M, int N, int K)
{
    __shared__ float As[16][128];
    __shared__ float Bs[16][128];
    const int tid = threadIdx.x;
    const int bx = blockIdx.x, by = blockIdx.y;
    const int tx = tid & 15, ty = tid >> 4;

    const int arow = tid >> 2;            // 0..63
    const int acol = (tid & 3) << 2;      // 0,4,8,12 (k within tile)
    const int brow = tid >> 5;            // 0..7 (k within tile)
    const int bcol = (tid & 31) << 2;     // 0..124

    const float* Aptr = A + (by * 128 + arow) * K + acol;
    const float* Bptr = Bm + brow * N + bx * 128 + bcol;

    float acc[8][8];
#pragma unroll
    for (int i = 0; i < 8; i++)
#pragma unroll
        for (int j = 0; j < 8; j++) acc[i][j] = 0.f;

    for (int kt = 0; kt < K; kt += 16) {
        float4 a0 = *(const float4*)(Aptr);
        float4 a1 = *(const float4*)(Aptr + 64 * K);
        float4 b0 = *(const float4*)(Bptr);
        float4 b1 = *(const float4*)(Bptr + 8 * N);
        As[acol + 0][arow] = a0.x;
        As[acol + 1][arow] = a0.y;
        As[acol + 2][arow] = a0.z;
        As[acol + 3][arow] = a0.w;
        As[acol + 0][arow + 64] = a1.x;
        As[acol + 1][arow + 64] = a1.y;
        As[acol + 2][arow + 64] = a1.z;
        As[acol + 3][arow + 64] = a1.w;
        *(float4*)(&Bs[brow][bcol]) = b0;
        *(float4*)(&Bs[brow + 8][bcol]) = b1;
        __syncthreads();
#pragma unroll
        for (int k = 0; k < 16; k++) {
            float ar[8], br[8];
            *(float4*)(ar)     = *(const float4*)(&As[k][ty * 8]);
            *(float4*)(ar + 4) = *(const float4*)(&As[k][ty * 8 + 4]);
            *(float4*)(br)     = *(const float4*)(&Bs[k][tx * 8]);
            *(float4*)(br + 4) = *(const float4*)(&Bs[k][tx * 8 + 4]);
#pragma unroll
            for (int i = 0; i < 8; i++)
#pragma unroll
                for (int j = 0; j < 8; j++)
                    acc[i][j] = fmaf(ar[i], br[j], acc[i][j]);
        }
        __syncthreads();
        Aptr += 16;
        Bptr += 16 * N;
    }

    const int row0 = by * 128 + ty * 8;
    const int col0 = bx * 128 + tx * 8;
    float bv[8];
#pragma unroll
    for (int j = 0; j < 8; j++) bv[j] = bias[col0 + j];
#pragma unroll
    for (int i = 0; i < 8; i++) {
        float4 v0, v1;
        v0.x = acc[i][0] + bv[0]; v0.y = acc[i][1] + bv[1];
        v0.z = acc[i][2] + bv[2]; v0.w = acc[i][3] + bv[3];
        v1.x = acc[i][4] + bv[4]; v1.y = acc[i][5] + bv[5];
        v1.z = acc[i][6] + bv[6]; v1.w = acc[i][7] + bv[7];
        *(float4*)(&Cc[(row0 + i) * N + col0])     = v0;
        *(float4*)(&Cc[(row0 + i) * N + col0 + 4]) = v1;
    }
}

__global__ __launch_bounds__(256) void k_qkv_gemm(const float* __restrict__ x,
                                                  const float* __restrict__ W,
                                                  const float* __restrict__ b)
{
    sgemm_body(x, W, b, g_qkv, T_DIM, F_DIM, C_DIM);
}

__global__ __launch_bounds__(256) void k_proj_gemm(const float* __restrict__ W,
                                                   const float* __restrict__ b,
                                                   float* __restrict__ out)
{
    sgemm_body(g_y, W, b, out, T_DIM, C_DIM, C_DIM);
}

// ---------------------------------------------------------------------------
// Causal flash attention, fp32.
// Block = 64 threads = 64 q-rows (one q-block). Each thread owns one q-row:
// q[64] and o[64] in registers, K/V 32x64 tiles in smem read via broadcast
// LDS.128 (all threads stream the same K/V row in lockstep -> conflict-free).
// Row-local online softmax: no cross-thread reductions at all.
// Blocks strictly above the diagonal are never visited.
// ---------------------------------------------------------------------------
__global__ __launch_bounds__(64) void k_flash()
{
    const int h  = blockIdx.y;
    const int qb = blockIdx.x;
    const int t  = threadIdx.x;
    const int qg = qb * 64 + t;

    __shared__ float Ks[32][68];   // pad 68 to de-conflict the fill stores
    __shared__ float Vs[32][68];

    float q[64];
    const float* qrow = g_qkv + (size_t)qg * F_DIM + h * 64;
#pragma unroll
    for (int d = 0; d < 64; d += 4) {
        float4 v = *(const float4*)(qrow + d);
        q[d] = v.x; q[d + 1] = v.y; q[d + 2] = v.z; q[d + 3] = v.w;
    }

    float o[64];
#pragma unroll
    for (int d = 0; d < 64; d++) o[d] = 0.f;
    float m = -1e30f, l = 0.f;

    const int nkb  = 2 * (qb + 1);     // 32-wide k-blocks covering [0, (qb+1)*64)
    const int r    = t >> 1;           // fill row
    const int half = (t & 1) * 32;     // fill half-row

    for (int j = 0; j < nkb; j++) {
        const int k0 = j * 32;
        const float* krow = g_qkv + (size_t)(k0 + r) * F_DIM + C_DIM     + h * 64 + half;
        const float* vrow = g_qkv + (size_t)(k0 + r) * F_DIM + 2 * C_DIM + h * 64 + half;
        __syncthreads();   // previous tile fully consumed before overwrite
#pragma unroll
        for (int d = 0; d < 32; d += 4) {
            *(float4*)(&Ks[r][half + d]) = *(const float4*)(krow + d);
            *(float4*)(&Vs[r][half + d]) = *(const float4*)(vrow + d);
        }
        __syncthreads();

        // S = q . K^T for 32 keys (causal predicate on the diagonal blocks)
        float s[32];
#pragma unroll
        for (int k = 0; k < 32; k++) {
            float acc = 0.f;
#pragma unroll
            for (int d = 0; d < 64; d += 4) {
                float4 kv = *(const float4*)(&Ks[k][d]);
                acc = fmaf(q[d],     kv.x, acc);
                acc = fmaf(q[d + 1], kv.y, acc);
                acc = fmaf(q[d + 2], kv.z, acc);
                acc = fmaf(q[d + 3], kv.w, acc);
            }
            s[k] = (k0 + k <= qg) ? acc * 0.125f : -1e30f;
        }

        // Online softmax (entirely thread-local)
        float mj = m;
#pragma unroll
        for (int k = 0; k < 32; k++) mj = fmaxf(mj, s[k]);
        const float corr = __expf(m - mj);
        m = mj;
        l *= corr;
#pragma unroll
        for (int d = 0; d < 64; d++) o[d] *= corr;

#pragma unroll
        for (int k = 0; k < 32; k++) {
            const float p = __expf(s[k] - mj);
            l += p;
#pragma unroll
            for (int d = 0; d < 64; d += 4) {
                float4 vv = *(const float4*)(&Vs[k][d]);
                o[d]     = fmaf(p, vv.x, o[d]);
                o[d + 1] = fmaf(p, vv.y, o[d + 1]);
                o[d + 2] = fmaf(p, vv.z, o[d + 2]);
                o[d + 3] = fmaf(p, vv.w, o[d + 3]);
            }
        }
    }

    const float inv = 1.f / l;
    float* yrow = g_y + (size_t)qg * C_DIM + h * 64;
#pragma unroll
    for (int d = 0; d < 64; d += 4) {
        float4 v;
        v.x = o[d] * inv; v.y = o[d + 1] * inv;
        v.z = o[d + 2] * inv; v.w = o[d + 3] * inv;
        *(float4*)(yrow + d) = v;
    }
}

// ---------------------------------------------------------------------------
// Launch: qkv GEMM -> flash attention -> proj GEMM (default stream, capturable)
// Inputs (metadata order): x, mask (unused; causality hardcoded), W_qkv,
// b_qkv, W_proj, b_proj. Output fp32 [1,4096,768].
// ---------------------------------------------------------------------------
extern "C" void kernel_launch(void* const* d_in, const int* in_sizes, int n_in,
                              void* d_out, int out_size)
{
    (void)in_sizes; (void)n_in; (void)out_size;
    const float* x      = (const float*)d_in[0];
    const float* W_qkv  = (const float*)d_in[2];
    const float* b_qkv  = (const float*)d_in[3];
    const float* W_proj = (const float*)d_in[4];
    const float* b_proj = (const float*)d_in[5];
    float* out = (float*)d_out;

    dim3 g1(F_DIM / 128, T_DIM / 128);   // (18, 32)
    k_qkv_gemm<<<g1, 256>>>(x, W_qkv, b_qkv);

    dim3 g2(T_DIM / 64, H_DIM);          // (64, 12)
    k_flash<<<g2, 64>>>();

    dim3 g3(C_DIM / 128, T_DIM / 128);   // (6, 32)
    k_proj_gemm<<<g3, 256>>>(W_proj, b_proj, out);
}

// round 3
// speedup vs baseline: 1.1398x; 1.1398x over previous
#include <cuda_runtime.h>

#define T_DIM 4096
#define C_DIM 768
#define H_DIM 12
#define D_DIM 64
#define F_DIM 2304   // 3*C

// Scratch (allocation-free: __device__ globals)
__device__ float g_qkv[T_DIM * F_DIM];   // [t][f] f: 0..767 Q, 768..1535 K, 1536..2303 V
__device__ float g_y[T_DIM * C_DIM];     // attention output [t][h*64+d]

// ---------------------------------------------------------------------------
// Generic 128x128x16 SGEMM body (unchanged from round 2).
// ---------------------------------------------------------------------------
__device__ __forceinline__ void sgemm_body(const float* __restrict__ A,
                                           const float* __restrict__ Bm,
                                           const float* __restrict__ bias,
                                           float* __restrict__ Cc,
                                           int M, int N, int K)
{
    __shared__ float As[16][128];
    __shared__ float Bs[16][128];
    const int tid = threadIdx.x;
    const int bx = blockIdx.x, by = blockIdx.y;
    const int tx = tid & 15, ty = tid >> 4;

    const int arow = tid >> 2;            // 0..63
    const int acol = (tid & 3) << 2;      // 0,4,8,12 (k within tile)
    const int brow = tid >> 5;            // 0..7 (k within tile)
    const int bcol = (tid & 31) << 2;     // 0..124

    const float* Aptr = A + (by * 128 + arow) * K + acol;
    const float* Bptr = Bm + brow * N + bx * 128 + bcol;

    float acc[8][8];
#pragma unroll
    for (int i = 0; i < 8; i++)
#pragma unroll
        for (int j = 0; j < 8; j++) acc[i][j] = 0.f;

    for (int kt = 0; kt < K; kt += 16) {
        float4 a0 = *(const float4*)(Aptr);
        float4 a1 = *(const float4*)(Aptr + 64 * K);
        float4 b0 = *(const float4*)(Bptr);
        float4 b1 = *(const float4*)(Bptr + 8 * N);
        As[acol + 0][arow] = a0.x;
        As[acol + 1][arow] = a0.y;
        As[acol + 2][arow] = a0.z;
        As[acol + 3][arow] = a0.w;
        As[acol + 0][arow + 64] = a1.x;
        As[acol + 1][arow + 64] = a1.y;
        As[acol + 2][arow + 64] = a1.z;
        As[acol + 3][arow + 64] = a1.w;
        *(float4*)(&Bs[brow][bcol]) = b0;
        *(float4*)(&Bs[brow + 8][bcol]) = b1;
        __syncthreads();
#pragma unroll
        for (int k = 0; k < 16; k++) {
            float ar[8], br[8];
            *(float4*)(ar)     = *(const float4*)(&As[k][ty * 8]);
            *(float4*)(ar + 4) = *(const float4*)(&As[k][ty * 8 + 4]);
            *(float4*)(br)     = *(const float4*)(&Bs[k][tx * 8]);
            *(float4*)(br + 4) = *(const float4*)(&Bs[k][tx * 8 + 4]);
#pragma unroll
            for (int i = 0; i < 8; i++)
#pragma unroll
                for (int j = 0; j < 8; j++)
                    acc[i][j] = fmaf(ar[i], br[j], acc[i][j]);
        }
        __syncthreads();
        Aptr += 16;
        Bptr += 16 * N;
    }

    const int row0 = by * 128 + ty * 8;
    const int col0 = bx * 128 + tx * 8;
    float bv[8];
#pragma unroll
    for (int j = 0; j < 8; j++) bv[j] = bias[col0 + j];
#pragma unroll
    for (int i = 0; i < 8; i++) {
        float4 v0, v1;
        v0.x = acc[i][0] + bv[0]; v0.y = acc[i][1] + bv[1];
        v0.z = acc[i][2] + bv[2]; v0.w = acc[i][3] + bv[3];
        v1.x = acc[i][4] + bv[4]; v1.y = acc[i][5] + bv[5];
        v1.z = acc[i][6] + bv[6]; v1.w = acc[i][7] + bv[7];
        *(float4*)(&Cc[(row0 + i) * N + col0])     = v0;
        *(float4*)(&Cc[(row0 + i) * N + col0 + 4]) = v1;
    }
}

__global__ __launch_bounds__(256) void k_qkv_gemm(const float* __restrict__ x,
                                                  const float* __restrict__ W,
                                                  const float* __restrict__ b)
{
    sgemm_body(x, W, b, g_qkv, T_DIM, F_DIM, C_DIM);
}

__global__ __launch_bounds__(256) void k_proj_gemm(const float* __restrict__ W,
                                                   const float* __restrict__ b,
                                                   float* __restrict__ out)
{
    sgemm_body(g_y, W, b, out, T_DIM, C_DIM, C_DIM);
}

// ---------------------------------------------------------------------------
// Causal flash attention, fp32, v2.
// Block = 64 threads = 64 q-rows. Each thread owns one q-row.
// QK now iterates d-OUTER over a transposed K tile (Kt[d][key], stride 36 ->
// conflict-free fill, broadcast reads), giving 32 independent s[k] accumulator
// chains (v1 had a single 64-long dependent chain -> latency bound).
// q is pre-scaled by 1/sqrt(D) at load. Heavy diagonal blocks launch first.
// ---------------------------------------------------------------------------
__global__ __launch_bounds__(64) void k_flash()
{
    const int h  = blockIdx.y;
    const int qb = gridDim.x - 1 - blockIdx.x;   // heavy blocks first
    const int t  = threadIdx.x;
    const int qg = qb * 64 + t;

    __shared__ float Kt[64][36];   // transposed K tile [d][key], pad 36 (16B-aligned rows)
    __shared__ float Vs[32][68];   // V tile key-major

    float q[64];
    const float* qrow = g_qkv + (size_t)qg * F_DIM + h * 64;
#pragma unroll
    for (int d = 0; d < 64; d += 4) {
        float4 v = *(const float4*)(qrow + d);
        q[d] = v.x * 0.125f; q[d + 1] = v.y * 0.125f;
        q[d + 2] = v.z * 0.125f; q[d + 3] = v.w * 0.125f;
    }

    float o[64];
#pragma unroll
    for (int d = 0; d < 64; d++) o[d] = 0.f;
    float m = -1e30f, l = 0.f;

    const int nkb  = 2 * (qb + 1);     // 32-wide k-blocks covering [0, (qb+1)*64)
    const int r    = t >> 1;           // fill row (key index in tile)
    const int half = (t & 1) * 32;     // fill half of d

    for (int j = 0; j < nkb; j++) {
        const int k0 = j * 32;
        const float* krow = g_qkv + (size_t)(k0 + r) * F_DIM + C_DIM     + h * 64 + half;
        const float* vrow = g_qkv + (size_t)(k0 + r) * F_DIM + 2 * C_DIM + h * 64 + half;
        __syncthreads();   // previous tile fully consumed before overwrite
#pragma unroll
        for (int d = 0; d < 32; d += 4) {
            float4 kv = *(const float4*)(krow + d);
            Kt[half + d + 0][r] = kv.x;
            Kt[half + d + 1][r] = kv.y;
            Kt[half + d + 2][r] = kv.z;
            Kt[half + d + 3][r] = kv.w;
            *(float4*)(&Vs[r][half + d]) = *(const float4*)(vrow + d);
        }
        __syncthreads();

        // S = q . K^T : d-outer, 32 independent accumulator chains
        float s[32];
#pragma unroll
        for (int k = 0; k < 32; k++) s[k] = 0.f;
#pragma unroll
        for (int d = 0; d < 64; d++) {
            const float qd = q[d];
#pragma unroll
            for (int kk = 0; kk < 32; kk += 4) {
                float4 kv = *(const float4*)(&Kt[d][kk]);
                s[kk + 0] = fmaf(qd, kv.x, s[kk + 0]);
                s[kk + 1] = fmaf(qd, kv.y, s[kk + 1]);
                s[kk + 2] = fmaf(qd, kv.z, s[kk + 2]);
                s[kk + 3] = fmaf(qd, kv.w, s[kk + 3]);
            }
        }

        // Causal mask (only the last two tiles of a q-block can straddle qg)
        if (k0 + 31 > qg) {
#pragma unroll
            for (int k = 0; k < 32; k++)
                if (k0 + k > qg) s[k] = -1e30f;
        }

        // Online softmax (entirely thread-local)
        float mj = m;
#pragma unroll
        for (int k = 0; k < 32; k++) mj = fmaxf(mj, s[k]);
        if (mj > m) {
            const float corr = __expf(m - mj);
            m = mj;
            l *= corr;
#pragma unroll
            for (int d = 0; d < 64; d++) o[d] *= corr;
        }

#pragma unroll
        for (int k = 0; k < 32; k++) {
            const float p = __expf(s[k] - mj);
            l += p;
#pragma unroll
            for (int d = 0; d < 64; d += 4) {
                float4 vv = *(const float4*)(&Vs[k][d]);
                o[d]     = fmaf(p, vv.x, o[d]);
                o[d + 1] = fmaf(p, vv.y, o[d + 1]);
                o[d + 2] = fmaf(p, vv.z, o[d + 2]);
                o[d + 3] = fmaf(p, vv.w, o[d + 3]);
            }
        }
    }

    const float inv = 1.f / l;
    float* yrow = g_y + (size_t)qg * C_DIM + h * 64;
#pragma unroll
    for (int d = 0; d < 64; d += 4) {
        float4 v;
        v.x = o[d] * inv; v.y = o[d + 1] * inv;
        v.z = o[d + 2] * inv; v.w = o[d + 3] * inv;
        *(float4*)(yrow + d) = v;
    }
}

// ---------------------------------------------------------------------------
// Launch: qkv GEMM -> flash attention -> proj GEMM (default stream, capturable)
// ---------------------------------------------------------------------------
extern "C" void kernel_launch(void* const* d_in, const int* in_sizes, int n_in,
                              void* d_out, int out_size)
{
    (void)in_sizes; (void)n_in; (void)out_size;
    const float* x      = (const float*)d_in[0];
    const float* W_qkv  = (const float*)d_in[2];
    const float* b_qkv  = (const float*)d_in[3];
    const float* W_proj = (const float*)d_in[4];
    const float* b_proj = (const float*)d_in[5];
    float* out = (float*)d_out;

    dim3 g1(F_DIM / 128, T_DIM / 128);   // (18, 32)
    k_qkv_gemm<<<g1, 256>>>(x, W_qkv, b_qkv);

    dim3 g2(T_DIM / 64, H_DIM);          // (64, 12)
    k_flash<<<g2, 64>>>();

    dim3 g3(C_DIM / 128, T_DIM / 128);   // (6, 32)
    k_proj_gemm<<<g3, 256>>>(W_proj, b_proj, out);
}

// round 4
// speedup vs baseline: 2.4281x; 2.1303x over previous
#include <cuda_runtime.h>

#define T_DIM 4096
#define C_DIM 768
#define H_DIM 12
#define D_DIM 64
#define F_DIM 2304   // 3*C

// Scratch (allocation-free: __device__ globals)
__device__ float g_qkv[T_DIM * F_DIM];   // [t][f] f: 0..767 Q, 768..1535 K, 1536..2303 V
__device__ float g_y[T_DIM * C_DIM];     // attention output [t][h*64+d]

// ---------------------------------------------------------------------------
// Generic 128x128x16 SGEMM body (unchanged).
// ---------------------------------------------------------------------------
__device__ __forceinline__ void sgemm_body(const float* __restrict__ A,
                                           const float* __restrict__ Bm,
                                           const float* __restrict__ bias,
                                           float* __restrict__ Cc,
                                           int M, int N, int K)
{
    __shared__ float As[16][128];
    __shared__ float Bs[16][128];
    const int tid = threadIdx.x;
    const int bx = blockIdx.x, by = blockIdx.y;
    const int tx = tid & 15, ty = tid >> 4;

    const int arow = tid >> 2;
    const int acol = (tid & 3) << 2;
    const int brow = tid >> 5;
    const int bcol = (tid & 31) << 2;

    const float* Aptr = A + (by * 128 + arow) * K + acol;
    const float* Bptr = Bm + brow * N + bx * 128 + bcol;

    float acc[8][8];
#pragma unroll
    for (int i = 0; i < 8; i++)
#pragma unroll
        for (int j = 0; j < 8; j++) acc[i][j] = 0.f;

    for (int kt = 0; kt < K; kt += 16) {
        float4 a0 = *(const float4*)(Aptr);
        float4 a1 = *(const float4*)(Aptr + 64 * K);
        float4 b0 = *(const float4*)(Bptr);
        float4 b1 = *(const float4*)(Bptr + 8 * N);
        As[acol + 0][arow] = a0.x;
        As[acol + 1][arow] = a0.y;
        As[acol + 2][arow] = a0.z;
        As[acol + 3][arow] = a0.w;
        As[acol + 0][arow + 64] = a1.x;
        As[acol + 1][arow + 64] = a1.y;
        As[acol + 2][arow + 64] = a1.z;
        As[acol + 3][arow + 64] = a1.w;
        *(float4*)(&Bs[brow][bcol]) = b0;
        *(float4*)(&Bs[brow + 8][bcol]) = b1;
        __syncthreads();
#pragma unroll
        for (int k = 0; k < 16; k++) {
            float ar[8], br[8];
            *(float4*)(ar)     = *(const float4*)(&As[k][ty * 8]);
            *(float4*)(ar + 4) = *(const float4*)(&As[k][ty * 8 + 4]);
            *(float4*)(br)     = *(const float4*)(&Bs[k][tx * 8]);
            *(float4*)(br + 4) = *(const float4*)(&Bs[k][tx * 8 + 4]);
#pragma unroll
            for (int i = 0; i < 8; i++)
#pragma unroll
                for (int j = 0; j < 8; j++)
                    acc[i][j] = fmaf(ar[i], br[j], acc[i][j]);
        }
        __syncthreads();
        Aptr += 16;
        Bptr += 16 * N;
    }

    const int row0 = by * 128 + ty * 8;
    const int col0 = bx * 128 + tx * 8;
    float bv[8];
#pragma unroll
    for (int j = 0; j < 8; j++) bv[j] = bias[col0 + j];
#pragma unroll
    for (int i = 0; i < 8; i++) {
        float4 v0, v1;
        v0.x = acc[i][0] + bv[0]; v0.y = acc[i][1] + bv[1];
        v0.z = acc[i][2] + bv[2]; v0.w = acc[i][3] + bv[3];
        v1.x = acc[i][4] + bv[4]; v1.y = acc[i][5] + bv[5];
        v1.z = acc[i][6] + bv[6]; v1.w = acc[i][7] + bv[7];
        *(float4*)(&Cc[(row0 + i) * N + col0])     = v0;
        *(float4*)(&Cc[(row0 + i) * N + col0 + 4]) = v1;
    }
}

__global__ __launch_bounds__(256) void k_qkv_gemm(const float* __restrict__ x,
                                                  const float* __restrict__ W,
                                                  const float* __restrict__ b)
{
    sgemm_body(x, W, b, g_qkv, T_DIM, F_DIM, C_DIM);
}

__global__ __launch_bounds__(256) void k_proj_gemm(const float* __restrict__ W,
                                                   const float* __restrict__ b,
                                                   float* __restrict__ out)
{
    sgemm_body(g_y, W, b, out, T_DIM, C_DIM, C_DIM);
}

// ---------------------------------------------------------------------------
// tf32 tensor-core helpers
// ---------------------------------------------------------------------------
__device__ __forceinline__ unsigned f2tf32(float x) {
    unsigned u;
    asm("cvt.rna.tf32.f32 %0, %1;" : "=r"(u) : "f"(x));
    return u;
}

__device__ __forceinline__ void mma_tf32(float& c0, float& c1, float& c2, float& c3,
                                         unsigned a0, unsigned a1, unsigned a2, unsigned a3,
                                         unsigned b0, unsigned b1)
{
    asm volatile("mma.sync.aligned.m16n8k8.row.col.f32.tf32.tf32.f32 "
                 "{%0,%1,%2,%3},{%4,%5,%6,%7},{%8,%9},{%0,%1,%2,%3};"
                 : "+f"(c0), "+f"(c1), "+f"(c2), "+f"(c3)
                 : "r"(a0), "r"(a1), "r"(a2), "r"(a3), "r"(b0), "r"(b1));
}

// ---------------------------------------------------------------------------
// Causal flash attention, tf32 tensor cores (mma.sync m16n8k8).
// Block = 128 threads (4 warps), 64 q-rows/block; warp w owns rows w*16..w*16+15.
// K-tile = 64 keys. Ks[key][d] stride 68 and Vt[d][key] stride 68 give
// conflict-free B-fragment LDS. P is re-fragmented C-layout -> A-layout with
// quad shuffles (no smem staging). Online softmax per 16-row warp fragment.
// ---------------------------------------------------------------------------
__global__ __launch_bounds__(128) void k_flash()
{
    const int h    = blockIdx.y;
    const int qb   = gridDim.x - 1 - blockIdx.x;   // heavy (late) q-blocks first
    const int tid  = threadIdx.x;
    const int w    = tid >> 5;
    const int lane = tid & 31;
    const int gi   = lane >> 2;     // group (row) id 0..7
    const int ti   = lane & 3;      // thread-in-group (col pair) 0..3

    __shared__ float Ks[64][68];    // [key][d]   (tf32 bit patterns)
    __shared__ float Vt[64][68];    // [d][key]   (tf32 bit patterns)

    // --- Q A-fragments (tf32), pre-scaled by 1/sqrt(D) ---
    unsigned qa[8][4];
    {
        const float* q0 = g_qkv + (size_t)(qb * 64 + w * 16 + gi) * F_DIM + h * 64;
        const float* q1 = q0 + 8 * F_DIM;
#pragma unroll
        for (int kc = 0; kc < 8; kc++) {
            const int c0 = kc * 8 + ti;
            qa[kc][0] = f2tf32(q0[c0]     * 0.125f);
            qa[kc][1] = f2tf32(q1[c0]     * 0.125f);
            qa[kc][2] = f2tf32(q0[c0 + 4] * 0.125f);
            qa[kc][3] = f2tf32(q1[c0 + 4] * 0.125f);
        }
    }

    float o[8][4];
#pragma unroll
    for (int n = 0; n < 8; n++) { o[n][0] = o[n][1] = o[n][2] = o[n][3] = 0.f; }
    float m0 = -1e30f, m1 = -1e30f, l0 = 0.f, l1 = 0.f;

    // fill assignments
    const int krow = tid >> 1;             // 0..63
    const int kcol = (tid & 1) * 32;       // 0 / 32
    const int vkey = tid & 63;             // 0..63
    const int vd0  = (tid >> 6) * 32;      // 0 / 32

    for (int j = 0; j <= qb; j++) {
        __syncthreads();   // previous tile fully consumed
        // --- fill K tile (row-major) ---
        {
            const float* src = g_qkv + (size_t)(j * 64 + krow) * F_DIM + C_DIM + h * 64 + kcol;
#pragma unroll
            for (int it = 0; it < 8; it++) {
                float4 v = *(const float4*)(src + it * 4);
                float4 t;
                t.x = __uint_as_float(f2tf32(v.x));
                t.y = __uint_as_float(f2tf32(v.y));
                t.z = __uint_as_float(f2tf32(v.z));
                t.w = __uint_as_float(f2tf32(v.w));
                *(float4*)(&Ks[krow][kcol + it * 4]) = t;
            }
        }
        // --- fill V tile (transposed) ---
        {
            const float* vsrc = g_qkv + (size_t)(j * 64 + vkey) * F_DIM + 2 * C_DIM + h * 64 + vd0;
#pragma unroll
            for (int it = 0; it < 8; it++) {
                float4 v = *(const float4*)(vsrc + it * 4);
                Vt[vd0 + it * 4 + 0][vkey] = __uint_as_float(f2tf32(v.x));
                Vt[vd0 + it * 4 + 1][vkey] = __uint_as_float(f2tf32(v.y));
                Vt[vd0 + it * 4 + 2][vkey] = __uint_as_float(f2tf32(v.z));
                Vt[vd0 + it * 4 + 3][vkey] = __uint_as_float(f2tf32(v.w));
            }
        }
        __syncthreads();

        // --- S = Q @ K^T  (8 d-chunks x 8 key-tiles of mma) ---
        float s[8][4];
#pragma unroll
        for (int n = 0; n < 8; n++) { s[n][0] = s[n][1] = s[n][2] = s[n][3] = 0.f; }
#pragma unroll
        for (int kc = 0; kc < 8; kc++) {
#pragma unroll
            for (int n = 0; n < 8; n++) {
                unsigned b0 = __float_as_uint(Ks[n * 8 + gi][kc * 8 + ti]);
                unsigned b1 = __float_as_uint(Ks[n * 8 + gi][kc * 8 + ti + 4]);
                mma_tf32(s[n][0], s[n][1], s[n][2], s[n][3],
                         qa[kc][0], qa[kc][1], qa[kc][2], qa[kc][3], b0, b1);
            }
        }

        // --- causal mask (diagonal tile only) ---
        if (j == qb) {
            const int r0l = w * 16 + gi;
            const int r1l = r0l + 8;
#pragma unroll
            for (int n = 0; n < 8; n++) {
                const int col = n * 8 + 2 * ti;
                if (col     > r0l) s[n][0] = -1e30f;
                if (col + 1 > r0l) s[n][1] = -1e30f;
                if (col     > r1l) s[n][2] = -1e30f;
                if (col + 1 > r1l) s[n][3] = -1e30f;
            }
        }

        // --- online softmax on fragments ---
        float rmax0 = -1e30f, rmax1 = -1e30f;
#pragma unroll
        for (int n = 0; n < 8; n++) {
            rmax0 = fmaxf(rmax0, fmaxf(s[n][0], s[n][1]));
            rmax1 = fmaxf(rmax1, fmaxf(s[n][2], s[n][3]));
        }
        rmax0 = fmaxf(rmax0, __shfl_xor_sync(0xffffffffu, rmax0, 1));
        rmax0 = fmaxf(rmax0, __shfl_xor_sync(0xffffffffu, rmax0, 2));
        rmax1 = fmaxf(rmax1, __shfl_xor_sync(0xffffffffu, rmax1, 1));
        rmax1 = fmaxf(rmax1, __shfl_xor_sync(0xffffffffu, rmax1, 2));

        const float mn0 = fmaxf(m0, rmax0);
        const float mn1 = fmaxf(m1, rmax1);
        const float corr0 = __expf(m0 - mn0);
        const float corr1 = __expf(m1 - mn1);
        m0 = mn0; m1 = mn1;

        float sum0 = 0.f, sum1 = 0.f;
#pragma unroll
        for (int n = 0; n < 8; n++) {
            float p00 = __expf(s[n][0] - mn0);
            float p01 = __expf(s[n][1] - mn0);
            float p10 = __expf(s[n][2] - mn1);
            float p11 = __expf(s[n][3] - mn1);
            sum0 += p00 + p01;
            sum1 += p10 + p11;
            // keep tf32 bit patterns in s[] for the PV fragments
            s[n][0] = __uint_as_float(f2tf32(p00));
            s[n][1] = __uint_as_float(f2tf32(p01));
            s[n][2] = __uint_as_float(f2tf32(p10));
            s[n][3] = __uint_as_float(f2tf32(p11));
        }
        sum0 += __shfl_xor_sync(0xffffffffu, sum0, 1);
        sum0 += __shfl_xor_sync(0xffffffffu, sum0, 2);
        sum1 += __shfl_xor_sync(0xffffffffu, sum1, 1);
        sum1 += __shfl_xor_sync(0xffffffffu, sum1, 2);
        l0 = l0 * corr0 + sum0;
        l1 = l1 * corr1 + sum1;

#pragma unroll
        for (int n = 0; n < 8; n++) {
            o[n][0] *= corr0; o[n][1] *= corr0;
            o[n][2] *= corr1; o[n][3] *= corr1;
        }

        // --- O += P @ V : re-fragment P (C-layout -> A-layout) via quad shuffles ---
        const int srcA = (lane & ~3) | (ti >> 1);   // owner of col ti      (within quad)
        const int srcB = srcA + 2;                  // owner of col ti + 4
#pragma unroll
        for (int kc = 0; kc < 8; kc++) {
            float x0 = __shfl_sync(0xffffffffu, s[kc][0], srcA);
            float x1 = __shfl_sync(0xffffffffu, s[kc][1], srcA);
            float x2 = __shfl_sync(0xffffffffu, s[kc][2], srcA);
            float x3 = __shfl_sync(0xffffffffu, s[kc][3], srcA);
            float y0 = __shfl_sync(0xffffffffu, s[kc][0], srcB);
            float y1 = __shfl_sync(0xffffffffu, s[kc][1], srcB);
            float y2 = __shfl_sync(0xffffffffu, s[kc][2], srcB);
            float y3 = __shfl_sync(0xffffffffu, s[kc][3], srcB);
            const bool odd = (ti & 1);
            unsigned a0 = __float_as_uint(odd ? x1 : x0);  // row gi,   col ti
            unsigned a1 = __float_as_uint(odd ? x3 : x2);  // row gi+8, col ti
            unsigned a2 = __float_as_uint(odd ? y1 : y0);  // row gi,   col ti+4
            unsigned a3 = __float_as_uint(odd ? y3 : y2);  // row gi+8, col ti+4
#pragma unroll
            for (int n = 0; n < 8; n++) {
                unsigned b0 = __float_as_uint(Vt[n * 8 + gi][kc * 8 + ti]);
                unsigned b1 = __float_as_uint(Vt[n * 8 + gi][kc * 8 + ti + 4]);
                mma_tf32(o[n][0], o[n][1], o[n][2], o[n][3],
                         a0, a1, a2, a3, b0, b1);
            }
        }
    }

    // --- normalize and write ---
    const float inv0 = 1.f / l0;
    const float inv1 = 1.f / l1;
    const int row0 = qb * 64 + w * 16 + gi;
    float* y0 = g_y + (size_t)row0 * C_DIM + h * 64;
    float* y1 = y0 + 8 * C_DIM;
#pragma unroll
    for (int n = 0; n < 8; n++) {
        float2 v0, v1;
        v0.x = o[n][0] * inv0; v0.y = o[n][1] * inv0;
        v1.x = o[n][2] * inv1; v1.y = o[n][3] * inv1;
        *(float2*)(y0 + n * 8 + 2 * ti) = v0;
        *(float2*)(y1 + n * 8 + 2 * ti) = v1;
    }
}

// ---------------------------------------------------------------------------
// Launch: qkv GEMM -> flash attention (tf32 mma) -> proj GEMM
// ---------------------------------------------------------------------------
extern "C" void kernel_launch(void* const* d_in, const int* in_sizes, int n_in,
                              void* d_out, int out_size)
{
    (void)in_sizes; (void)n_in; (void)out_size;
    const float* x      = (const float*)d_in[0];
    const float* W_qkv  = (const float*)d_in[2];
    const float* b_qkv  = (const float*)d_in[3];
    const float* W_proj = (const float*)d_in[4];
    const float* b_proj = (const float*)d_in[5];
    float* out = (float*)d_out;

    dim3 g1(F_DIM / 128, T_DIM / 128);   // (18, 32)
    k_qkv_gemm<<<g1, 256>>>(x, W_qkv, b_qkv);

    dim3 g2(T_DIM / 64, H_DIM);          // (64, 12)
    k_flash<<<g2, 128>>>();

    dim3 g3(C_DIM / 128, T_DIM / 128);   // (6, 32)
    k_proj_gemm<<<g3, 256>>>(W_proj, b_proj, out);
}

// round 5
// speedup vs baseline: 3.0709x; 1.2647x over previous
#include <cuda_runtime.h>

#define T_DIM 4096
#define C_DIM 768
#define H_DIM 12
#define D_DIM 64
#define F_DIM 2304   // 3*C

// Scratch (allocation-free: __device__ globals)
__device__ float g_qkv[T_DIM * F_DIM];   // [t][f] f: 0..767 Q, 768..1535 K, 1536..2303 V
__device__ float g_y[T_DIM * C_DIM];     // attention output [t][h*64+d]

// ---------------------------------------------------------------------------
// tf32 tensor-core helpers
// ---------------------------------------------------------------------------
__device__ __forceinline__ unsigned f2tf32(float x) {
    unsigned u;
    asm("cvt.rna.tf32.f32 %0, %1;" : "=r"(u) : "f"(x));
    return u;
}

__device__ __forceinline__ void mma_tf32(float& c0, float& c1, float& c2, float& c3,
                                         unsigned a0, unsigned a1, unsigned a2, unsigned a3,
                                         unsigned b0, unsigned b1)
{
    asm volatile("mma.sync.aligned.m16n8k8.row.col.f32.tf32.tf32.f32 "
                 "{%0,%1,%2,%3},{%4,%5,%6,%7},{%8,%9},{%0,%1,%2,%3};"
                 : "+f"(c0), "+f"(c1), "+f"(c2), "+f"(c3)
                 : "r"(a0), "r"(a1), "r"(a2), "r"(a3), "r"(b0), "r"(b1));
}

// ---------------------------------------------------------------------------
// tf32 tensor-core GEMM: C = A[MxK] @ B[KxN] + bias (row-major).
// A is split hi+lo (2 MMAs) so activations are fp32-exact; B carries one tf32
// rounding (~2.4e-4). 256 thr / 8 warps, 128x128 block tile, 64x32 warp tile.
// Smem stride 136 -> fragment LDS reads conflict-free ({8*ti+gi} mod 32).
// ---------------------------------------------------------------------------
__device__ __forceinline__ void gemm_tf32_body(const float* __restrict__ A,
                                               const float* __restrict__ Bm,
                                               const float* __restrict__ bias,
                                               float* __restrict__ Cc,
                                               int M, int N, int K)
{
    __shared__ float Ah[16][136];   // tf32(a) bit patterns, [k][m]
    __shared__ float Al[16][136];   // tf32(a - hi)
    __shared__ float Bs[16][136];   // tf32(b), [k][n]

    const int tid  = threadIdx.x;
    const int bx   = blockIdx.x, by = blockIdx.y;
    const int w    = tid >> 5;
    const int lane = tid & 31;
    const int gi   = lane >> 2;
    const int ti   = lane & 3;
    const int wm   = (w & 1) * 64;   // warp m-offset within tile
    const int wn   = (w >> 1) * 32;  // warp n-offset within tile

    // fill indices
    const int arow = tid >> 2;            // 0..63 (m)
    const int acol = (tid & 3) << 2;      // 0,4,8,12 (k)
    const int brow = tid >> 5;            // 0..7 (k)
    const int bcol = (tid & 31) << 2;     // 0..124 (n)

    const float* Aptr = A + (size_t)(by * 128 + arow) * K + acol;
    const float* Bptr = Bm + (size_t)brow * N + bx * 128 + bcol;

    float acc[4][4][4];
#pragma unroll
    for (int i = 0; i < 4; i++)
#pragma unroll
        for (int j = 0; j < 4; j++)
#pragma unroll
            for (int c = 0; c < 4; c++) acc[i][j][c] = 0.f;

    for (int kt = 0; kt < K; kt += 16) {
        float4 a0 = *(const float4*)(Aptr);
        float4 a1 = *(const float4*)(Aptr + (size_t)64 * K);
        float4 b0 = *(const float4*)(Bptr);
        float4 b1 = *(const float4*)(Bptr + (size_t)8 * N);
        __syncthreads();   // previous tile consumed
        {
            float va[4] = {a0.x, a0.y, a0.z, a0.w};
            float vb[4] = {a1.x, a1.y, a1.z, a1.w};
#pragma unroll
            for (int e = 0; e < 4; e++) {
                float hif = __uint_as_float(f2tf32(va[e]));
                Ah[acol + e][arow] = hif;
                Al[acol + e][arow] = __uint_as_float(f2tf32(va[e] - hif));
                float hif2 = __uint_as_float(f2tf32(vb[e]));
                Ah[acol + e][arow + 64] = hif2;
                Al[acol + e][arow + 64] = __uint_as_float(f2tf32(vb[e] - hif2));
            }
            float4 t0, t1;
            t0.x = __uint_as_float(f2tf32(b0.x)); t0.y = __uint_as_float(f2tf32(b0.y));
            t0.z = __uint_as_float(f2tf32(b0.z)); t0.w = __uint_as_float(f2tf32(b0.w));
            t1.x = __uint_as_float(f2tf32(b1.x)); t1.y = __uint_as_float(f2tf32(b1.y));
            t1.z = __uint_as_float(f2tf32(b1.z)); t1.w = __uint_as_float(f2tf32(b1.w));
            *(float4*)(&Bs[brow][bcol])     = t0;
            *(float4*)(&Bs[brow + 8][bcol]) = t1;
        }
        __syncthreads();

#pragma unroll
        for (int k8 = 0; k8 < 16; k8 += 8) {
            unsigned bf[4][2];
#pragma unroll
            for (int nf = 0; nf < 4; nf++) {
                const int n0 = wn + nf * 8 + gi;
                bf[nf][0] = __float_as_uint(Bs[k8 + ti][n0]);
                bf[nf][1] = __float_as_uint(Bs[k8 + ti + 4][n0]);
            }
            unsigned ah[4][4], al[4][4];
#pragma unroll
            for (int mf = 0; mf < 4; mf++) {
                const int m0 = wm + mf * 16 + gi;
                ah[mf][0] = __float_as_uint(Ah[k8 + ti][m0]);
                ah[mf][1] = __float_as_uint(Ah[k8 + ti][m0 + 8]);
                ah[mf][2] = __float_as_uint(Ah[k8 + ti + 4][m0]);
                ah[mf][3] = __float_as_uint(Ah[k8 + ti + 4][m0 + 8]);
                al[mf][0] = __float_as_uint(Al[k8 + ti][m0]);
                al[mf][1] = __float_as_uint(Al[k8 + ti][m0 + 8]);
                al[mf][2] = __float_as_uint(Al[k8 + ti + 4][m0]);
                al[mf][3] = __float_as_uint(Al[k8 + ti + 4][m0 + 8]);
            }
#pragma unroll
            for (int mf = 0; mf < 4; mf++)
#pragma unroll
                for (int nf = 0; nf < 4; nf++) {
                    mma_tf32(acc[mf][nf][0], acc[mf][nf][1], acc[mf][nf][2], acc[mf][nf][3],
                             ah[mf][0], ah[mf][1], ah[mf][2], ah[mf][3],
                             bf[nf][0], bf[nf][1]);
                    mma_tf32(acc[mf][nf][0], acc[mf][nf][1], acc[mf][nf][2], acc[mf][nf][3],
                             al[mf][0], al[mf][1], al[mf][2], al[mf][3],
                             bf[nf][0], bf[nf][1]);
                }
        }
        Aptr += 16;
        Bptr += (size_t)16 * N;
    }

    // epilogue: C-layout frag rows gi/gi+8, cols 2ti/2ti+1
#pragma unroll
    for (int mf = 0; mf < 4; mf++) {
        const int row = by * 128 + wm + mf * 16 + gi;
#pragma unroll
        for (int nf = 0; nf < 4; nf++) {
            const int col = bx * 128 + wn + nf * 8 + 2 * ti;
            const float bv0 = bias[col], bv1 = bias[col + 1];
            float2 v0, v1;
            v0.x = acc[mf][nf][0] + bv0; v0.y = acc[mf][nf][1] + bv1;
            v1.x = acc[mf][nf][2] + bv0; v1.y = acc[mf][nf][3] + bv1;
            *(float2*)(&Cc[(size_t)row * N + col])       = v0;
            *(float2*)(&Cc[(size_t)(row + 8) * N + col]) = v1;
        }
    }
}

__global__ __launch_bounds__(256, 2) void k_qkv_gemm(const float* __restrict__ x,
                                                     const float* __restrict__ W,
                                                     const float* __restrict__ b)
{
    gemm_tf32_body(x, W, b, g_qkv, T_DIM, F_DIM, C_DIM);
}

__global__ __launch_bounds__(256, 2) void k_proj_gemm(const float* __restrict__ W,
                                                      const float* __restrict__ b,
                                                      float* __restrict__ out)
{
    gemm_tf32_body(g_y, W, b, out, T_DIM, C_DIM, C_DIM);
}

// ---------------------------------------------------------------------------
// Causal flash attention, tf32 tensor cores (unchanged from round 4).
// ---------------------------------------------------------------------------
__global__ __launch_bounds__(128) void k_flash()
{
    const int h    = blockIdx.y;
    const int qb   = gridDim.x - 1 - blockIdx.x;   // heavy (late) q-blocks first
    const int tid  = threadIdx.x;
    const int w    = tid >> 5;
    const int lane = tid & 31;
    const int gi   = lane >> 2;
    const int ti   = lane & 3;

    __shared__ float Ks[64][68];    // [key][d]   (tf32 bit patterns)
    __shared__ float Vt[64][68];    // [d][key]   (tf32 bit patterns)

    unsigned qa[8][4];
    {
        const float* q0 = g_qkv + (size_t)(qb * 64 + w * 16 + gi) * F_DIM + h * 64;
        const float* q1 = q0 + 8 * F_DIM;
#pragma unroll
        for (int kc = 0; kc < 8; kc++) {
            const int c0 = kc * 8 + ti;
            qa[kc][0] = f2tf32(q0[c0]     * 0.125f);
            qa[kc][1] = f2tf32(q1[c0]     * 0.125f);
            qa[kc][2] = f2tf32(q0[c0 + 4] * 0.125f);
            qa[kc][3] = f2tf32(q1[c0 + 4] * 0.125f);
        }
    }

    float o[8][4];
#pragma unroll
    for (int n = 0; n < 8; n++) { o[n][0] = o[n][1] = o[n][2] = o[n][3] = 0.f; }
    float m0 = -1e30f, m1 = -1e30f, l0 = 0.f, l1 = 0.f;

    const int krow = tid >> 1;
    const int kcol = (tid & 1) * 32;
    const int vkey = tid & 63;
    const int vd0  = (tid >> 6) * 32;

    for (int j = 0; j <= qb; j++) {
        __syncthreads();
        {
            const float* src = g_qkv + (size_t)(j * 64 + krow) * F_DIM + C_DIM + h * 64 + kcol;
#pragma unroll
            for (int it = 0; it < 8; it++) {
                float4 v = *(const float4*)(src + it * 4);
                float4 t;
                t.x = __uint_as_float(f2tf32(v.x));
                t.y = __uint_as_float(f2tf32(v.y));
                t.z = __uint_as_float(f2tf32(v.z));
                t.w = __uint_as_float(f2tf32(v.w));
                *(float4*)(&Ks[krow][kcol + it * 4]) = t;
            }
        }
        {
            const float* vsrc = g_qkv + (size_t)(j * 64 + vkey) * F_DIM + 2 * C_DIM + h * 64 + vd0;
#pragma unroll
            for (int it = 0; it < 8; it++) {
                float4 v = *(const float4*)(vsrc + it * 4);
                Vt[vd0 + it * 4 + 0][vkey] = __uint_as_float(f2tf32(v.x));
                Vt[vd0 + it * 4 + 1][vkey] = __uint_as_float(f2tf32(v.y));
                Vt[vd0 + it * 4 + 2][vkey] = __uint_as_float(f2tf32(v.z));
                Vt[vd0 + it * 4 + 3][vkey] = __uint_as_float(f2tf32(v.w));
            }
        }
        __syncthreads();

        float s[8][4];
#pragma unroll
        for (int n = 0; n < 8; n++) { s[n][0] = s[n][1] = s[n][2] = s[n][3] = 0.f; }
#pragma unroll
        for (int kc = 0; kc < 8; kc++) {
#pragma unroll
            for (int n = 0; n < 8; n++) {
                unsigned b0 = __float_as_uint(Ks[n * 8 + gi][kc * 8 + ti]);
                unsigned b1 = __float_as_uint(Ks[n * 8 + gi][kc * 8 + ti + 4]);
                mma_tf32(s[n][0], s[n][1], s[n][2], s[n][3],
                         qa[kc][0], qa[kc][1], qa[kc][2], qa[kc][3], b0, b1);
            }
        }

        if (j == qb) {
            const int r0l = w * 16 + gi;
            const int r1l = r0l + 8;
#pragma unroll
            for (int n = 0; n < 8; n++) {
                const int col = n * 8 + 2 * ti;
                if (col     > r0l) s[n][0] = -1e30f;
                if (col + 1 > r0l) s[n][1] = -1e30f;
                if (col     > r1l) s[n][2] = -1e30f;
                if (col + 1 > r1l) s[n][3] = -1e30f;
            }
        }

        float rmax0 = -1e30f, rmax1 = -1e30f;
#pragma unroll
        for (int n = 0; n < 8; n++) {
            rmax0 = fmaxf(rmax0, fmaxf(s[n][0], s[n][1]));
            rmax1 = fmaxf(rmax1, fmaxf(s[n][2], s[n][3]));
        }
        rmax0 = fmaxf(rmax0, __shfl_xor_sync(0xffffffffu, rmax0, 1));
        rmax0 = fmaxf(rmax0, __shfl_xor_sync(0xffffffffu, rmax0, 2));
        rmax1 = fmaxf(rmax1, __shfl_xor_sync(0xffffffffu, rmax1, 1));
        rmax1 = fmaxf(rmax1, __shfl_xor_sync(0xffffffffu, rmax1, 2));

        const float mn0 = fmaxf(m0, rmax0);
        const float mn1 = fmaxf(m1, rmax1);
        const float corr0 = __expf(m0 - mn0);
        const float corr1 = __expf(m1 - mn1);
        m0 = mn0; m1 = mn1;

        float sum0 = 0.f, sum1 = 0.f;
#pragma unroll
        for (int n = 0; n < 8; n++) {
            float p00 = __expf(s[n][0] - mn0);
            float p01 = __expf(s[n][1] - mn0);
            float p10 = __expf(s[n][2] - mn1);
            float p11 = __expf(s[n][3] - mn1);
            sum0 += p00 + p01;
            sum1 += p10 + p11;
            s[n][0] = __uint_as_float(f2tf32(p00));
            s[n][1] = __uint_as_float(f2tf32(p01));
            s[n][2] = __uint_as_float(f2tf32(p10));
            s[n][3] = __uint_as_float(f2tf32(p11));
        }
        sum0 += __shfl_xor_sync(0xffffffffu, sum0, 1);
        sum0 += __shfl_xor_sync(0xffffffffu, sum0, 2);
        sum1 += __shfl_xor_sync(0xffffffffu, sum1, 1);
        sum1 += __shfl_xor_sync(0xffffffffu, sum1, 2);
        l0 = l0 * corr0 + sum0;
        l1 = l1 * corr1 + sum1;

#pragma unroll
        for (int n = 0; n < 8; n++) {
            o[n][0] *= corr0; o[n][1] *= corr0;
            o[n][2] *= corr1; o[n][3] *= corr1;
        }

        const int srcA = (lane & ~3) | (ti >> 1);
        const int srcB = srcA + 2;
#pragma unroll
        for (int kc = 0; kc < 8; kc++) {
            float x0 = __shfl_sync(0xffffffffu, s[kc][0], srcA);
            float x1 = __shfl_sync(0xffffffffu, s[kc][1], srcA);
            float x2 = __shfl_sync(0xffffffffu, s[kc][2], srcA);
            float x3 = __shfl_sync(0xffffffffu, s[kc][3], srcA);
            float y0 = __shfl_sync(0xffffffffu, s[kc][0], srcB);
            float y1 = __shfl_sync(0xffffffffu, s[kc][1], srcB);
            float y2 = __shfl_sync(0xffffffffu, s[kc][2], srcB);
            float y3 = __shfl_sync(0xffffffffu, s[kc][3], srcB);
            const bool odd = (ti & 1);
            unsigned a0 = __float_as_uint(odd ? x1 : x0);
            unsigned a1 = __float_as_uint(odd ? x3 : x2);
            unsigned a2 = __float_as_uint(odd ? y1 : y0);
            unsigned a3 = __float_as_uint(odd ? y3 : y2);
#pragma unroll
            for (int n = 0; n < 8; n++) {
                unsigned b0 = __float_as_uint(Vt[n * 8 + gi][kc * 8 + ti]);
                unsigned b1 = __float_as_uint(Vt[n * 8 + gi][kc * 8 + ti + 4]);
                mma_tf32(o[n][0], o[n][1], o[n][2], o[n][3],
                         a0, a1, a2, a3, b0, b1);
            }
        }
    }

    const float inv0 = 1.f / l0;
    const float inv1 = 1.f / l1;
    const int row0 = qb * 64 + w * 16 + gi;
    float* y0 = g_y + (size_t)row0 * C_DIM + h * 64;
    float* y1 = y0 + 8 * C_DIM;
#pragma unroll
    for (int n = 0; n < 8; n++) {
        float2 v0, v1;
        v0.x = o[n][0] * inv0; v0.y = o[n][1] * inv0;
        v1.x = o[n][2] * inv1; v1.y = o[n][3] * inv1;
        *(float2*)(y0 + n * 8 + 2 * ti) = v0;
        *(float2*)(y1 + n * 8 + 2 * ti) = v1;
    }
}

// ---------------------------------------------------------------------------
// Launch: qkv GEMM (tf32 mma) -> flash attention (tf32 mma) -> proj GEMM
// ---------------------------------------------------------------------------
extern "C" void kernel_launch(void* const* d_in, const int* in_sizes, int n_in,
                              void* d_out, int out_size)
{
    (void)in_sizes; (void)n_in; (void)out_size;
    const float* x      = (const float*)d_in[0];
    const float* W_qkv  = (const float*)d_in[2];
    const float* b_qkv  = (const float*)d_in[3];
    const float* W_proj = (const float*)d_in[4];
    const float* b_proj = (const float*)d_in[5];
    float* out = (float*)d_out;

    dim3 g1(F_DIM / 128, T_DIM / 128);   // (18, 32)
    k_qkv_gemm<<<g1, 256>>>(x, W_qkv, b_qkv);

    dim3 g2(T_DIM / 64, H_DIM);          // (64, 12)
    k_flash<<<g2, 128>>>();

    dim3 g3(C_DIM / 128, T_DIM / 128);   // (6, 32)
    k_proj_gemm<<<g3, 256>>>(W_proj, b_proj, out);
}

// round 7
// speedup vs baseline: 5.0645x; 1.6492x over previous
#include <cuda_runtime.h>
#include <cuda_fp16.h>

#define T_DIM 4096
#define C_DIM 768
#define H_DIM 12
#define D_DIM 64
#define F_DIM 2304   // 3*C

// Scratch (allocation-free: __device__ globals)
__device__ float  g_qkv[T_DIM * F_DIM];          // [t][f] Q|K|V fp32
__device__ float  g_y[T_DIM * C_DIM];            // attention output
__device__ __half g_k16[H_DIM * T_DIM * D_DIM];  // K fp16 [h][t][d]
__device__ __half g_v16t[H_DIM * D_DIM * T_DIM]; // V fp16 transposed [h][d][t]

// ---------------------------------------------------------------------------
// helpers
// ---------------------------------------------------------------------------
__device__ __forceinline__ unsigned h2_as_u32(__half2 v) {
    unsigned u;
    memcpy(&u, &v, 4);
    return u;
}

__device__ __forceinline__ unsigned f2tf32(float x) {
    unsigned u;
    asm("cvt.rna.tf32.f32 %0, %1;" : "=r"(u) : "f"(x));
    return u;
}

__device__ __forceinline__ void mma_tf32(float& c0, float& c1, float& c2, float& c3,
                                         unsigned a0, unsigned a1, unsigned a2, unsigned a3,
                                         unsigned b0, unsigned b1)
{
    asm volatile("mma.sync.aligned.m16n8k8.row.col.f32.tf32.tf32.f32 "
                 "{%0,%1,%2,%3},{%4,%5,%6,%7},{%8,%9},{%0,%1,%2,%3};"
                 : "+f"(c0), "+f"(c1), "+f"(c2), "+f"(c3)
                 : "r"(a0), "r"(a1), "r"(a2), "r"(a3), "r"(b0), "r"(b1));
}

__device__ __forceinline__ void mma_f16(float& c0, float& c1, float& c2, float& c3,
                                        unsigned a0, unsigned a1, unsigned a2, unsigned a3,
                                        unsigned b0, unsigned b1)
{
    asm volatile("mma.sync.aligned.m16n8k16.row.col.f32.f16.f16.f32 "
                 "{%0,%1,%2,%3},{%4,%5,%6,%7},{%8,%9},{%0,%1,%2,%3};"
                 : "+f"(c0), "+f"(c1), "+f"(c2), "+f"(c3)
                 : "r"(a0), "r"(a1), "r"(a2), "r"(a3), "r"(b0), "r"(b1));
}

__device__ __forceinline__ void cp_async16(void* smem_dst, const void* gmem_src)
{
    unsigned dst = (unsigned)__cvta_generic_to_shared(smem_dst);
    asm volatile("cp.async.cg.shared.global [%0], [%1], 16;" :: "r"(dst), "l"(gmem_src));
}

// ---------------------------------------------------------------------------
// tf32 tensor-core GEMM (unchanged from round 5)
// ---------------------------------------------------------------------------
__device__ __forceinline__ void gemm_tf32_body(const float* __restrict__ A,
                                               const float* __restrict__ Bm,
                                               const float* __restrict__ bias,
                                               float* __restrict__ Cc,
                                               int M, int N, int K)
{
    __shared__ float Ah[16][136];
    __shared__ float Al[16][136];
    __shared__ float Bs[16][136];

    const int tid  = threadIdx.x;
    const int bx   = blockIdx.x, by = blockIdx.y;
    const int w    = tid >> 5;
    const int lane = tid & 31;
    const int gi   = lane >> 2;
    const int ti   = lane & 3;
    const int wm   = (w & 1) * 64;
    const int wn   = (w >> 1) * 32;

    const int arow = tid >> 2;
    const int acol = (tid & 3) << 2;
    const int brow = tid >> 5;
    const int bcol = (tid & 31) << 2;

    const float* Aptr = A + (size_t)(by * 128 + arow) * K + acol;
    const float* Bptr = Bm + (size_t)brow * N + bx * 128 + bcol;

    float acc[4][4][4];
#pragma unroll
    for (int i = 0; i < 4; i++)
#pragma unroll
        for (int j = 0; j < 4; j++)
#pragma unroll
            for (int c = 0; c < 4; c++) acc[i][j][c] = 0.f;

    for (int kt = 0; kt < K; kt += 16) {
        float4 a0 = *(const float4*)(Aptr);
        float4 a1 = *(const float4*)(Aptr + (size_t)64 * K);
        float4 b0 = *(const float4*)(Bptr);
        float4 b1 = *(const float4*)(Bptr + (size_t)8 * N);
        __syncthreads();
        {
            float va[4] = {a0.x, a0.y, a0.z, a0.w};
            float vb[4] = {a1.x, a1.y, a1.z, a1.w};
#pragma unroll
            for (int e = 0; e < 4; e++) {
                float hif = __uint_as_float(f2tf32(va[e]));
                Ah[acol + e][arow] = hif;
                Al[acol + e][arow] = __uint_as_float(f2tf32(va[e] - hif));
                float hif2 = __uint_as_float(f2tf32(vb[e]));
                Ah[acol + e][arow + 64] = hif2;
                Al[acol + e][arow + 64] = __uint_as_float(f2tf32(vb[e] - hif2));
            }
            float4 t0, t1;
            t0.x = __uint_as_float(f2tf32(b0.x)); t0.y = __uint_as_float(f2tf32(b0.y));
            t0.z = __uint_as_float(f2tf32(b0.z)); t0.w = __uint_as_float(f2tf32(b0.w));
            t1.x = __uint_as_float(f2tf32(b1.x)); t1.y = __uint_as_float(f2tf32(b1.y));
            t1.z = __uint_as_float(f2tf32(b1.z)); t1.w = __uint_as_float(f2tf32(b1.w));
            *(float4*)(&Bs[brow][bcol])     = t0;
            *(float4*)(&Bs[brow + 8][bcol]) = t1;
        }
        __syncthreads();

#pragma unroll
        for (int k8 = 0; k8 < 16; k8 += 8) {
            unsigned bf[4][2];
#pragma unroll
            for (int nf = 0; nf < 4; nf++) {
                const int n0 = wn + nf * 8 + gi;
                bf[nf][0] = __float_as_uint(Bs[k8 + ti][n0]);
                bf[nf][1] = __float_as_uint(Bs[k8 + ti + 4][n0]);
            }
            unsigned ah[4][4], al[4][4];
#pragma unroll
            for (int mf = 0; mf < 4; mf++) {
                const int m0 = wm + mf * 16 + gi;
                ah[mf][0] = __float_as_uint(Ah[k8 + ti][m0]);
                ah[mf][1] = __float_as_uint(Ah[k8 + ti][m0 + 8]);
                ah[mf][2] = __float_as_uint(Ah[k8 + ti + 4][m0]);
                ah[mf][3] = __float_as_uint(Ah[k8 + ti + 4][m0 + 8]);
                al[mf][0] = __float_as_uint(Al[k8 + ti][m0]);
                al[mf][1] = __float_as_uint(Al[k8 + ti][m0 + 8]);
                al[mf][2] = __float_as_uint(Al[k8 + ti + 4][m0]);
                al[mf][3] = __float_as_uint(Al[k8 + ti + 4][m0 + 8]);
            }
#pragma unroll
            for (int mf = 0; mf < 4; mf++)
#pragma unroll
                for (int nf = 0; nf < 4; nf++) {
                    mma_tf32(acc[mf][nf][0], acc[mf][nf][1], acc[mf][nf][2], acc[mf][nf][3],
                             ah[mf][0], ah[mf][1], ah[mf][2], ah[mf][3],
                             bf[nf][0], bf[nf][1]);
                    mma_tf32(acc[mf][nf][0], acc[mf][nf][1], acc[mf][nf][2], acc[mf][nf][3],
                             al[mf][0], al[mf][1], al[mf][2], al[mf][3],
                             bf[nf][0], bf[nf][1]);
                }
        }
        Aptr += 16;
        Bptr += (size_t)16 * N;
    }

#pragma unroll
    for (int mf = 0; mf < 4; mf++) {
        const int row = by * 128 + wm + mf * 16 + gi;
#pragma unroll
        for (int nf = 0; nf < 4; nf++) {
            const int col = bx * 128 + wn + nf * 8 + 2 * ti;
            const float bv0 = bias[col], bv1 = bias[col + 1];
            float2 v0, v1;
            v0.x = acc[mf][nf][0] + bv0; v0.y = acc[mf][nf][1] + bv1;
            v1.x = acc[mf][nf][2] + bv0; v1.y = acc[mf][nf][3] + bv1;
            *(float2*)(&Cc[(size_t)row * N + col])       = v0;
            *(float2*)(&Cc[(size_t)(row + 8) * N + col]) = v1;
        }
    }
}

__global__ __launch_bounds__(256, 2) void k_qkv_gemm(const float* __restrict__ x,
                                                     const float* __restrict__ W,
                                                     const float* __restrict__ b)
{
    gemm_tf32_body(x, W, b, g_qkv, T_DIM, F_DIM, C_DIM);
}

__global__ __launch_bounds__(256, 2) void k_proj_gemm(const float* __restrict__ W,
                                                      const float* __restrict__ b,
                                                      float* __restrict__ out)
{
    gemm_tf32_body(g_y, W, b, out, T_DIM, C_DIM, C_DIM);
}

// ---------------------------------------------------------------------------
// Pre-convert K -> fp16 [h][t][d]  (8 halves per thread, coalesced both sides)
// ---------------------------------------------------------------------------
__global__ __launch_bounds__(256) void k_cvtK()
{
    const int idx = blockIdx.x * 256 + threadIdx.x;          // 393216 threads
    const int flat8 = idx * 8;                               // half index
    const int h = flat8 >> 18;                               // / (4096*64)
    const int rem = flat8 & 262143;
    const int t = rem >> 6;
    const int d = rem & 63;
    const float* src = g_qkv + (size_t)t * F_DIM + C_DIM + h * 64 + d;
    float4 a = *(const float4*)(src);
    float4 b = *(const float4*)(src + 4);
    uint4 o;
    o.x = h2_as_u32(__floats2half2_rn(a.x, a.y));
    o.y = h2_as_u32(__floats2half2_rn(a.z, a.w));
    o.z = h2_as_u32(__floats2half2_rn(b.x, b.y));
    o.w = h2_as_u32(__floats2half2_rn(b.z, b.w));
    *(uint4*)(&g_k16[flat8]) = o;
}

// ---------------------------------------------------------------------------
// Pre-convert V -> fp16 transposed [h][d][t] via smem-tiled 64x64 transpose
// ---------------------------------------------------------------------------
__global__ __launch_bounds__(256) void k_cvtV()
{
    __shared__ __half S[64][72];
    const int tid = threadIdx.x;
    const int t0  = blockIdx.x * 64;
    const int h   = blockIdx.y;

    // load 64t x 64d (coalesced), convert to half
    {
        const int tr = tid >> 2;
        const int dp = (tid & 3) << 4;
        const float* src = g_qkv + (size_t)(t0 + tr) * F_DIM + 2 * C_DIM + h * 64 + dp;
#pragma unroll
        for (int e = 0; e < 4; e++) {
            float4 v = *(const float4*)(src + 4 * e);
            __half2 p0 = __floats2half2_rn(v.x, v.y);
            __half2 p1 = __floats2half2_rn(v.z, v.w);
            *(__half2*)(&S[tr][dp + 4 * e])     = p0;
            *(__half2*)(&S[tr][dp + 4 * e + 2]) = p1;
        }
    }
    __syncthreads();
    // write transposed (coalesced in t)
    {
        const int d  = tid >> 2;
        const int tp = (tid & 3) << 4;
        __half* dst = g_v16t + ((size_t)h * 64 + d) * T_DIM + t0 + tp;
#pragma unroll
        for (int e = 0; e < 8; e++) {
            __half2 v = __halves2half2(S[tp + 2 * e][d], S[tp + 2 * e + 1][d]);
            *(__half2*)(dst + 2 * e) = v;
        }
    }
}

// ---------------------------------------------------------------------------
// Causal flash attention, fp16 tensor cores (m16n8k16), double-buffered
// cp.async K/V tiles. Block = 128 threads (4 warps), 64 q-rows; 64-key tiles.
// C-layout of S == A-layout of P (f16 k16) -> zero-shuffle re-fragmentation.
// ---------------------------------------------------------------------------
__global__ __launch_bounds__(128) void k_flash()
{
    const int h    = blockIdx.y;
    const int qb   = gridDim.x - 1 - blockIdx.x;   // heavy (late) q-blocks first
    const int tid  = threadIdx.x;
    const int w    = tid >> 5;
    const int lane = tid & 31;
    const int gi   = lane >> 2;
    const int ti   = lane & 3;

    __shared__ __align__(16) __half Ks[2][64][72];   // [buf][key][d]
    __shared__ __align__(16) __half Vt[2][64][72];   // [buf][d][key]

    // Q A-fragments (fp16), pre-scaled by 1/sqrt(D)
    unsigned qa[4][4];
    {
        const float* q0 = g_qkv + (size_t)(qb * 64 + w * 16 + gi) * F_DIM + h * 64;
        const float* q1 = q0 + 8 * F_DIM;
#pragma unroll
        for (int kc = 0; kc < 4; kc++) {
            const int c0 = kc * 16 + 2 * ti;
            qa[kc][0] = h2_as_u32(__floats2half2_rn(q0[c0] * 0.125f,     q0[c0 + 1] * 0.125f));
            qa[kc][1] = h2_as_u32(__floats2half2_rn(q1[c0] * 0.125f,     q1[c0 + 1] * 0.125f));
            qa[kc][2] = h2_as_u32(__floats2half2_rn(q0[c0 + 8] * 0.125f, q0[c0 + 9] * 0.125f));
            qa[kc][3] = h2_as_u32(__floats2half2_rn(q1[c0 + 8] * 0.125f, q1[c0 + 9] * 0.125f));
        }
    }

    float o[8][4];
#pragma unroll
    for (int n = 0; n < 8; n++) { o[n][0] = o[n][1] = o[n][2] = o[n][3] = 0.f; }
    float m0 = -1e30f, m1 = -1e30f, l0 = 0.f, l1 = 0.f;

    const __half* kbase = g_k16 + (size_t)h * T_DIM * 64;
    const __half* vbase = g_v16t + (size_t)h * 64 * T_DIM;
    const int frow = tid >> 1;              // key (for K) / d (for V)
    const int fcol = (tid & 1) * 32;        // 32-half chunk

    // produce tile j into buffer buf (8 x 16B cp.async per thread)
    auto produce = [&](int j, int buf) {
        const __half* ksrc = kbase + (size_t)(j * 64 + frow) * 64 + fcol;
        __half* kdst = &Ks[buf][frow][fcol];
#pragma unroll
        for (int e = 0; e < 4; e++) cp_async16(kdst + 8 * e, ksrc + 8 * e);
        const __half* vsrc = vbase + (size_t)frow * T_DIM + j * 64 + fcol;
        __half* vdst = &Vt[buf][frow][fcol];
#pragma unroll
        for (int e = 0; e < 4; e++) cp_async16(vdst + 8 * e, vsrc + 8 * e);
        asm volatile("cp.async.commit_group;" ::: "memory");
    };

    produce(0, 0);

    for (int j = 0; j <= qb; j++) {
        asm volatile("cp.async.wait_group 0;" ::: "memory");
        __syncthreads();                       // tile j visible to all; prev buf consumed
        if (j < qb) produce(j + 1, (j + 1) & 1);
        const int buf = j & 1;

        // --- S = Q @ K^T : 4 k16-chunks x 8 key-tiles ---
        float s[8][4];
#pragma unroll
        for (int n = 0; n < 8; n++) { s[n][0] = s[n][1] = s[n][2] = s[n][3] = 0.f; }
#pragma unroll
        for (int kc = 0; kc < 4; kc++) {
#pragma unroll
            for (int n = 0; n < 8; n++) {
                unsigned b0 = *(const unsigned*)(&Ks[buf][n * 8 + gi][kc * 16 + 2 * ti]);
                unsigned b1 = *(const unsigned*)(&Ks[buf][n * 8 + gi][kc * 16 + 2 * ti + 8]);
                mma_f16(s[n][0], s[n][1], s[n][2], s[n][3],
                        qa[kc][0], qa[kc][1], qa[kc][2], qa[kc][3], b0, b1);
            }
        }

        // --- causal mask (diagonal block only) ---
        if (j == qb) {
            const int r0l = w * 16 + gi;
            const int r1l = r0l + 8;
#pragma unroll
            for (int n = 0; n < 8; n++) {
                const int col = n * 8 + 2 * ti;
                if (col     > r0l) s[n][0] = -1e30f;
                if (col + 1 > r0l) s[n][1] = -1e30f;
                if (col     > r1l) s[n][2] = -1e30f;
                if (col + 1 > r1l) s[n][3] = -1e30f;
            }
        }

        // --- online softmax ---
        float rmax0 = -1e30f, rmax1 = -1e30f;
#pragma unroll
        for (int n = 0; n < 8; n++) {
            rmax0 = fmaxf(rmax0, fmaxf(s[n][0], s[n][1]));
            rmax1 = fmaxf(rmax1, fmaxf(s[n][2], s[n][3]));
        }
        rmax0 = fmaxf(rmax0, __shfl_xor_sync(0xffffffffu, rmax0, 1));
        rmax0 = fmaxf(rmax0, __shfl_xor_sync(0xffffffffu, rmax0, 2));
        rmax1 = fmaxf(rmax1, __shfl_xor_sync(0xffffffffu, rmax1, 1));
        rmax1 = fmaxf(rmax1, __shfl_xor_sync(0xffffffffu, rmax1, 2));

        const float mn0 = fmaxf(m0, rmax0);
        const float mn1 = fmaxf(m1, rmax1);
        const float corr0 = __expf(m0 - mn0);
        const float corr1 = __expf(m1 - mn1);
        m0 = mn0; m1 = mn1;

        unsigned ph[8][2];   // P as half2 fragments (C-layout == A-layout)
        float sum0 = 0.f, sum1 = 0.f;
#pragma unroll
        for (int n = 0; n < 8; n++) {
            float p00 = __expf(s[n][0] - mn0);
            float p01 = __expf(s[n][1] - mn0);
            float p10 = __expf(s[n][2] - mn1);
            float p11 = __expf(s[n][3] - mn1);
            sum0 += p00 + p01;
            sum1 += p10 + p11;
            ph[n][0] = h2_as_u32(__floats2half2_rn(p00, p01));
            ph[n][1] = h2_as_u32(__floats2half2_rn(p10, p11));
        }
        sum0 += __shfl_xor_sync(0xffffffffu, sum0, 1);
        sum0 += __shfl_xor_sync(0xffffffffu, sum0, 2);
        sum1 += __shfl_xor_sync(0xffffffffu, sum1, 1);
        sum1 += __shfl_xor_sync(0xffffffffu, sum1, 2);
        l0 = l0 * corr0 + sum0;
        l1 = l1 * corr1 + sum1;

#pragma unroll
        for (int n = 0; n < 8; n++) {
            o[n][0] *= corr0; o[n][1] *= corr0;
            o[n][2] *= corr1; o[n][3] *= corr1;
        }

        // --- O += P @ V : A-frags come straight from ph (no shuffles) ---
#pragma unroll
        for (int kc = 0; kc < 4; kc++) {
            unsigned a0 = ph[2 * kc][0];
            unsigned a1 = ph[2 * kc][1];
            unsigned a2 = ph[2 * kc + 1][0];
            unsigned a3 = ph[2 * kc + 1][1];
#pragma unroll
            for (int n = 0; n < 8; n++) {
                unsigned b0 = *(const unsigned*)(&Vt[buf][n * 8 + gi][kc * 16 + 2 * ti]);
                unsigned b1 = *(const unsigned*)(&Vt[buf][n * 8 + gi][kc * 16 + 2 * ti + 8]);
                mma_f16(o[n][0], o[n][1], o[n][2], o[n][3], a0, a1, a2, a3, b0, b1);
            }
        }
    }

    // --- normalize and write ---
    const float inv0 = 1.f / l0;
    const float inv1 = 1.f / l1;
    const int row0 = qb * 64 + w * 16 + gi;
    float* y0 = g_y + (size_t)row0 * C_DIM + h * 64;
    float* y1 = y0 + 8 * C_DIM;
#pragma unroll
    for (int n = 0; n < 8; n++) {
        float2 v0, v1;
        v0.x = o[n][0] * inv0; v0.y = o[n][1] * inv0;
        v1.x = o[n][2] * inv1; v1.y = o[n][3] * inv1;
        *(float2*)(y0 + n * 8 + 2 * ti) = v0;
        *(float2*)(y1 + n * 8 + 2 * ti) = v1;
    }
}

// ---------------------------------------------------------------------------
// Launch: qkv GEMM -> K/V fp16 pre-convert -> flash (fp16 mma) -> proj GEMM
// ---------------------------------------------------------------------------
extern "C" void kernel_launch(void* const* d_in, const int* in_sizes, int n_in,
                              void* d_out, int out_size)
{
    (void)in_sizes; (void)n_in; (void)out_size;
    const float* x      = (const float*)d_in[0];
    const float* W_qkv  = (const float*)d_in[2];
    const float* b_qkv  = (const float*)d_in[3];
    const float* W_proj = (const float*)d_in[4];
    const float* b_proj = (const float*)d_in[5];
    float* out = (float*)d_out;

    dim3 g1(F_DIM / 128, T_DIM / 128);   // (18, 32)
    k_qkv_gemm<<<g1, 256>>>(x, W_qkv, b_qkv);

    k_cvtK<<<1536, 256>>>();
    dim3 gv(T_DIM / 64, H_DIM);          // (64, 12)
    k_cvtV<<<gv, 256>>>();

    dim3 g2(T_DIM / 64, H_DIM);          // (64, 12)
    k_flash<<<g2, 128>>>();

    dim3 g3(C_DIM / 128, T_DIM / 128);   // (6, 32)
    k_proj_gemm<<<g3, 256>>>(W_proj, b_proj, out);
}

// round 9
// speedup vs baseline: 6.3693x; 1.2576x over previous
#include <cuda_runtime.h>
#include <cuda_fp16.h>

#define T_DIM 4096
#define C_DIM 768
#define H_DIM 12
#define D_DIM 64
#define F_DIM 2304   // 3*C

// Scratch (allocation-free: __device__ globals)
__device__ float  g_qkv[T_DIM * F_DIM];          // [t][f] Q|K|V fp32
__device__ float  g_y[T_DIM * C_DIM];            // attention output
__device__ __half g_k16[H_DIM * T_DIM * D_DIM];  // K fp16 [h][t][d]
__device__ __half g_v16t[H_DIM * D_DIM * T_DIM]; // V fp16 transposed [h][d][t]
__device__ __half g_ah[T_DIM * C_DIM];           // GEMM A hi fp16 [m][k]
__device__ __half g_al[T_DIM * C_DIM];           // GEMM A lo fp16 [m][k]
__device__ __half g_bt[C_DIM * F_DIM];           // GEMM B^T fp16 [n][k]

// ---------------------------------------------------------------------------
// helpers
// ---------------------------------------------------------------------------
__device__ __forceinline__ unsigned h2_as_u32(__half2 v) {
    unsigned u;
    memcpy(&u, &v, 4);
    return u;
}

__device__ __forceinline__ void mma_f16(float& c0, float& c1, float& c2, float& c3,
                                        unsigned a0, unsigned a1, unsigned a2, unsigned a3,
                                        unsigned b0, unsigned b1)
{
    asm volatile("mma.sync.aligned.m16n8k16.row.col.f32.f16.f16.f32 "
                 "{%0,%1,%2,%3},{%4,%5,%6,%7},{%8,%9},{%0,%1,%2,%3};"
                 : "+f"(c0), "+f"(c1), "+f"(c2), "+f"(c3)
                 : "r"(a0), "r"(a1), "r"(a2), "r"(a3), "r"(b0), "r"(b1));
}

__device__ __forceinline__ void cp_async16(void* smem_dst, const void* gmem_src)
{
    unsigned dst = (unsigned)__cvta_generic_to_shared(smem_dst);
    asm volatile("cp.async.cg.shared.global [%0], [%1], 16;" :: "r"(dst), "l"(gmem_src));
}

// ---------------------------------------------------------------------------
// Operand pre-conversion kernels
// ---------------------------------------------------------------------------
// fp32 -> fp16 hi + lo split (hi+lo reproduces ~22 mantissa bits)
__global__ __launch_bounds__(256) void k_cvtA(const float* __restrict__ src,
                                              __half* __restrict__ dh,
                                              __half* __restrict__ dl)
{
    const size_t i8 = ((size_t)blockIdx.x * 256 + threadIdx.x) * 8;
    float4 a = *(const float4*)(src + i8);
    float4 b = *(const float4*)(src + i8 + 4);
    float v[8] = {a.x, a.y, a.z, a.w, b.x, b.y, b.z, b.w};
    __half hs[8], ls[8];
#pragma unroll
    for (int e = 0; e < 8; e++) {
        __half hi = __float2half_rn(v[e]);
        hs[e] = hi;
        ls[e] = __float2half_rn(v[e] - __half2float(hi));
    }
    uint4 oh, ol;
    oh.x = h2_as_u32(__halves2half2(hs[0], hs[1]));
    oh.y = h2_as_u32(__halves2half2(hs[2], hs[3]));
    oh.z = h2_as_u32(__halves2half2(hs[4], hs[5]));
    oh.w = h2_as_u32(__halves2half2(hs[6], hs[7]));
    ol.x = h2_as_u32(__halves2half2(ls[0], ls[1]));
    ol.y = h2_as_u32(__halves2half2(ls[2], ls[3]));
    ol.z = h2_as_u32(__halves2half2(ls[4], ls[5]));
    ol.w = h2_as_u32(__halves2half2(ls[6], ls[7]));
    *(uint4*)(&dh[i8]) = oh;
    *(uint4*)(&dl[i8]) = ol;
}

// W [K][N] fp32 -> W^T [N][K] fp16 (32x32 smem tiles, both sides coalesced)
__global__ __launch_bounds__(256) void k_cvtWt(const float* __restrict__ W,
                                               __half* __restrict__ Wt,
                                               int K, int N)
{
    __shared__ __half S[32][33];
    const int tx = threadIdx.x & 31;
    const int ty = threadIdx.x >> 5;
    const int n0 = blockIdx.x * 32;
    const int k0 = blockIdx.y * 32;
#pragma unroll
    for (int e = 0; e < 4; e++)
        S[ty + 8 * e][tx] = __float2half_rn(W[(size_t)(k0 + ty + 8 * e) * N + n0 + tx]);
    __syncthreads();
#pragma unroll
    for (int e = 0; e < 4; e++)
        Wt[(size_t)(n0 + ty + 8 * e) * K + k0 + tx] = S[tx][ty + 8 * e];
}

// ---------------------------------------------------------------------------
// fp16 hi/lo tensor-core GEMM: C = A @ B + bias.
// A given as hi/lo fp16 [M][K]; B given transposed fp16 [N][K]; C fp32 [M][N].
// 256 thr / 8 warps, 128x128 tile, 64x32 warp tile, K-tile 16, 2-stage
// cp.async double buffer. Stride-24 smem rows -> conflict-free u32 frag LDS.
// ---------------------------------------------------------------------------
__global__ __launch_bounds__(256, 2) void k_gemm16(const __half* __restrict__ Ahg,
                                                   const __half* __restrict__ Alg,
                                                   const __half* __restrict__ Btg,
                                                   const float* __restrict__ bias,
                                                   float* __restrict__ Cc,
                                                   int N, int K)
{
    __shared__ __align__(16) __half Ah[2][128][24];
    __shared__ __align__(16) __half Al[2][128][24];
    __shared__ __align__(16) __half Bs[2][128][24];

    const int tid  = threadIdx.x;
    const int bx   = blockIdx.x, by = blockIdx.y;
    const int w    = tid >> 5;
    const int lane = tid & 31;
    const int gi   = lane >> 2;
    const int ti   = lane & 3;
    const int wm   = (w & 1) * 64;
    const int wn   = (w >> 1) * 32;

    const int frow = tid >> 1;          // 0..127
    const int fofs = (tid & 1) * 8;     // 0 / 8

    const __half* aSrcH = Ahg + (size_t)(by * 128 + frow) * K + fofs;
    const __half* aSrcL = Alg + (size_t)(by * 128 + frow) * K + fofs;
    const __half* bSrc  = Btg + (size_t)(bx * 128 + frow) * K + fofs;

    auto produce = [&](int stage) {
        const int buf = stage & 1;
        const int k0 = stage * 16;
        cp_async16(&Ah[buf][frow][fofs], aSrcH + k0);
        cp_async16(&Al[buf][frow][fofs], aSrcL + k0);
        cp_async16(&Bs[buf][frow][fofs], bSrc + k0);
        asm volatile("cp.async.commit_group;" ::: "memory");
    };

    float acc[4][4][4];
#pragma unroll
    for (int i = 0; i < 4; i++)
#pragma unroll
        for (int j = 0; j < 4; j++)
#pragma unroll
            for (int c = 0; c < 4; c++) acc[i][j][c] = 0.f;

    const int NS = K / 16;
    produce(0);

    for (int s = 0; s < NS; s++) {
        if (s + 1 < NS) {
            produce(s + 1);
            asm volatile("cp.async.wait_group 1;" ::: "memory");
        } else {
            asm volatile("cp.async.wait_group 0;" ::: "memory");
        }
        __syncthreads();
        const int buf = s & 1;

        unsigned bf[4][2];
#pragma unroll
        for (int nf = 0; nf < 4; nf++) {
            const int n0 = wn + nf * 8 + gi;
            bf[nf][0] = *(const unsigned*)(&Bs[buf][n0][2 * ti]);
            bf[nf][1] = *(const unsigned*)(&Bs[buf][n0][2 * ti + 8]);
        }
        unsigned ah[4][4], alr[4][4];
#pragma unroll
        for (int mf = 0; mf < 4; mf++) {
            const int m0 = wm + mf * 16 + gi;
            ah[mf][0]  = *(const unsigned*)(&Ah[buf][m0][2 * ti]);
            ah[mf][1]  = *(const unsigned*)(&Ah[buf][m0 + 8][2 * ti]);
            ah[mf][2]  = *(const unsigned*)(&Ah[buf][m0][2 * ti + 8]);
            ah[mf][3]  = *(const unsigned*)(&Ah[buf][m0 + 8][2 * ti + 8]);
            alr[mf][0] = *(const unsigned*)(&Al[buf][m0][2 * ti]);
            alr[mf][1] = *(const unsigned*)(&Al[buf][m0 + 8][2 * ti]);
            alr[mf][2] = *(const unsigned*)(&Al[buf][m0][2 * ti + 8]);
            alr[mf][3] = *(const unsigned*)(&Al[buf][m0 + 8][2 * ti + 8]);
        }
#pragma unroll
        for (int mf = 0; mf < 4; mf++)
#pragma unroll
            for (int nf = 0; nf < 4; nf++) {
                mma_f16(acc[mf][nf][0], acc[mf][nf][1], acc[mf][nf][2], acc[mf][nf][3],
                        ah[mf][0], ah[mf][1], ah[mf][2], ah[mf][3],
                        bf[nf][0], bf[nf][1]);
                mma_f16(acc[mf][nf][0], acc[mf][nf][1], acc[mf][nf][2], acc[mf][nf][3],
                        alr[mf][0], alr[mf][1], alr[mf][2], alr[mf][3],
                        bf[nf][0], bf[nf][1]);
            }
        __syncthreads();
    }

    // epilogue: frag rows gi/gi+8, cols 2ti/2ti+1
#pragma unroll
    for (int mf = 0; mf < 4; mf++) {
        const int row = by * 128 + wm + mf * 16 + gi;
#pragma unroll
        for (int nf = 0; nf < 4; nf++) {
            const int col = bx * 128 + wn + nf * 8 + 2 * ti;
            const float bv0 = bias[col], bv1 = bias[col + 1];
            float2 v0, v1;
            v0.x = acc[mf][nf][0] + bv0; v0.y = acc[mf][nf][1] + bv1;
            v1.x = acc[mf][nf][2] + bv0; v1.y = acc[mf][nf][3] + bv1;
            *(float2*)(&Cc[(size_t)row * N + col])       = v0;
            *(float2*)(&Cc[(size_t)(row + 8) * N + col]) = v1;
        }
    }
}

// ---------------------------------------------------------------------------
// Pre-convert K -> fp16 [h][t][d]
// ---------------------------------------------------------------------------
__global__ __launch_bounds__(256) void k_cvtK()
{
    const int idx = blockIdx.x * 256 + threadIdx.x;
    const int flat8 = idx * 8;
    const int h = flat8 >> 18;
    const int rem = flat8 & 262143;
    const int t = rem >> 6;
    const int d = rem & 63;
    const float* src = g_qkv + (size_t)t * F_DIM + C_DIM + h * 64 + d;
    float4 a = *(const float4*)(src);
    float4 b = *(const float4*)(src + 4);
    uint4 o;
    o.x = h2_as_u32(__floats2half2_rn(a.x, a.y));
    o.y = h2_as_u32(__floats2half2_rn(a.z, a.w));
    o.z = h2_as_u32(__floats2half2_rn(b.x, b.y));
    o.w = h2_as_u32(__floats2half2_rn(b.z, b.w));
    *(uint4*)(&g_k16[flat8]) = o;
}

// ---------------------------------------------------------------------------
// Pre-convert V -> fp16 transposed [h][d][t]
// ---------------------------------------------------------------------------
__global__ __launch_bounds__(256) void k_cvtV()
{
    __shared__ __half S[64][72];
    const int tid = threadIdx.x;
    const int t0  = blockIdx.x * 64;
    const int h   = blockIdx.y;
    {
        const int tr = tid >> 2;
        const int dp = (tid & 3) << 4;
        const float* src = g_qkv + (size_t)(t0 + tr) * F_DIM + 2 * C_DIM + h * 64 + dp;
#pragma unroll
        for (int e = 0; e < 4; e++) {
            float4 v = *(const float4*)(src + 4 * e);
            __half2 p0 = __floats2half2_rn(v.x, v.y);
            __half2 p1 = __floats2half2_rn(v.z, v.w);
            *(__half2*)(&S[tr][dp + 4 * e])     = p0;
            *(__half2*)(&S[tr][dp + 4 * e + 2]) = p1;
        }
    }
    __syncthreads();
    {
        const int d  = tid >> 2;
        const int tp = (tid & 3) << 4;
        __half* dst = g_v16t + ((size_t)h * 64 + d) * T_DIM + t0 + tp;
#pragma unroll
        for (int e = 0; e < 8; e++) {
            __half2 v = __halves2half2(S[tp + 2 * e][d], S[tp + 2 * e + 1][d]);
            *(__half2*)(dst + 2 * e) = v;
        }
    }
}

// ---------------------------------------------------------------------------
// Causal flash attention, fp16 tensor cores (unchanged from round 7)
// ---------------------------------------------------------------------------
__global__ __launch_bounds__(128) void k_flash()
{
    const int h    = blockIdx.y;
    const int qb   = gridDim.x - 1 - blockIdx.x;
    const int tid  = threadIdx.x;
    const int w    = tid >> 5;
    const int lane = tid & 31;
    const int gi   = lane >> 2;
    const int ti   = lane & 3;

    __shared__ __align__(16) __half Ks[2][64][72];
    __shared__ __align__(16) __half Vt[2][64][72];

    unsigned qa[4][4];
    {
        const float* q0 = g_qkv + (size_t)(qb * 64 + w * 16 + gi) * F_DIM + h * 64;
        const float* q1 = q0 + 8 * F_DIM;
#pragma unroll
        for (int kc = 0; kc < 4; kc++) {
            const int c0 = kc * 16 + 2 * ti;
            qa[kc][0] = h2_as_u32(__floats2half2_rn(q0[c0] * 0.125f,     q0[c0 + 1] * 0.125f));
            qa[kc][1] = h2_as_u32(__floats2half2_rn(q1[c0] * 0.125f,     q1[c0 + 1] * 0.125f));
            qa[kc][2] = h2_as_u32(__floats2half2_rn(q0[c0 + 8] * 0.125f, q0[c0 + 9] * 0.125f));
            qa[kc][3] = h2_as_u32(__floats2half2_rn(q1[c0 + 8] * 0.125f, q1[c0 + 9] * 0.125f));
        }
    }

    float o[8][4];
#pragma unroll
    for (int n = 0; n < 8; n++) { o[n][0] = o[n][1] = o[n][2] = o[n][3] = 0.f; }
    float m0 = -1e30f, m1 = -1e30f, l0 = 0.f, l1 = 0.f;

    const __half* kbase = g_k16 + (size_t)h * T_DIM * 64;
    const __half* vbase = g_v16t + (size_t)h * 64 * T_DIM;
    const int frow = tid >> 1;
    const int fcol = (tid & 1) * 32;

    auto produce = [&](int j, int buf) {
        const __half* ksrc = kbase + (size_t)(j * 64 + frow) * 64 + fcol;
        __half* kdst = &Ks[buf][frow][fcol];
#pragma unroll
        for (int e = 0; e < 4; e++) cp_async16(kdst + 8 * e, ksrc + 8 * e);
        const __half* vsrc = vbase + (size_t)frow * T_DIM + j * 64 + fcol;
        __half* vdst = &Vt[buf][frow][fcol];
#pragma unroll
        for (int e = 0; e < 4; e++) cp_async16(vdst + 8 * e, vsrc + 8 * e);
        asm volatile("cp.async.commit_group;" ::: "memory");
    };

    produce(0, 0);

    for (int j = 0; j <= qb; j++) {
        asm volatile("cp.async.wait_group 0;" ::: "memory");
        __syncthreads();
        if (j < qb) produce(j + 1, (j + 1) & 1);
        const int buf = j & 1;

        float s[8][4];
#pragma unroll
        for (int n = 0; n < 8; n++) { s[n][0] = s[n][1] = s[n][2] = s[n][3] = 0.f; }
#pragma unroll
        for (int kc = 0; kc < 4; kc++) {
#pragma unroll
            for (int n = 0; n < 8; n++) {
                unsigned b0 = *(const unsigned*)(&Ks[buf][n * 8 + gi][kc * 16 + 2 * ti]);
                unsigned b1 = *(const unsigned*)(&Ks[buf][n * 8 + gi][kc * 16 + 2 * ti + 8]);
                mma_f16(s[n][0], s[n][1], s[n][2], s[n][3],
                        qa[kc][0], qa[kc][1], qa[kc][2], qa[kc][3], b0, b1);
            }
        }

        if (j == qb) {
            const int r0l = w * 16 + gi;
            const int r1l = r0l + 8;
#pragma unroll
            for (int n = 0; n < 8; n++) {
                const int col = n * 8 + 2 * ti;
                if (col     > r0l) s[n][0] = -1e30f;
                if (col + 1 > r0l) s[n][1] = -1e30f;
                if (col     > r1l) s[n][2] = -1e30f;
                if (col + 1 > r1l) s[n][3] = -1e30f;
            }
        }

        float rmax0 = -1e30f, rmax1 = -1e30f;
#pragma unroll
        for (int n = 0; n < 8; n++) {
            rmax0 = fmaxf(rmax0, fmaxf(s[n][0], s[n][1]));
            rmax1 = fmaxf(rmax1, fmaxf(s[n][2], s[n][3]));
        }
        rmax0 = fmaxf(rmax0, __shfl_xor_sync(0xffffffffu, rmax0, 1));
        rmax0 = fmaxf(rmax0, __shfl_xor_sync(0xffffffffu, rmax0, 2));
        rmax1 = fmaxf(rmax1, __shfl_xor_sync(0xffffffffu, rmax1, 1));
        rmax1 = fmaxf(rmax1, __shfl_xor_sync(0xffffffffu, rmax1, 2));

        const float mn0 = fmaxf(m0, rmax0);
        const float mn1 = fmaxf(m1, rmax1);
        const float corr0 = __expf(m0 - mn0);
        const float corr1 = __expf(m1 - mn1);
        m0 = mn0; m1 = mn1;

        unsigned ph[8][2];
        float sum0 = 0.f, sum1 = 0.f;
#pragma unroll
        for (int n = 0; n < 8; n++) {
            float p00 = __expf(s[n][0] - mn0);
            float p01 = __expf(s[n][1] - mn0);
            float p10 = __expf(s[n][2] - mn1);
            float p11 = __expf(s[n][3] - mn1);
            sum0 += p00 + p01;
            sum1 += p10 + p11;
            ph[n][0] = h2_as_u32(__floats2half2_rn(p00, p01));
            ph[n][1] = h2_as_u32(__floats2half2_rn(p10, p11));
        }
        sum0 += __shfl_xor_sync(0xffffffffu, sum0, 1);
        sum0 += __shfl_xor_sync(0xffffffffu, sum0, 2);
        sum1 += __shfl_xor_sync(0xffffffffu, sum1, 1);
        sum1 += __shfl_xor_sync(0xffffffffu, sum1, 2);
        l0 = l0 * corr0 + sum0;
        l1 = l1 * corr1 + sum1;

#pragma unroll
        for (int n = 0; n < 8; n++) {
            o[n][0] *= corr0; o[n][1] *= corr0;
            o[n][2] *= corr1; o[n][3] *= corr1;
        }

#pragma unroll
        for (int kc = 0; kc < 4; kc++) {
            unsigned a0 = ph[2 * kc][0];
            unsigned a1 = ph[2 * kc][1];
            unsigned a2 = ph[2 * kc + 1][0];
            unsigned a3 = ph[2 * kc + 1][1];
#pragma unroll
            for (int n = 0; n < 8; n++) {
                unsigned b0 = *(const unsigned*)(&Vt[buf][n * 8 + gi][kc * 16 + 2 * ti]);
                unsigned b1 = *(const unsigned*)(&Vt[buf][n * 8 + gi][kc * 16 + 2 * ti + 8]);
                mma_f16(o[n][0], o[n][1], o[n][2], o[n][3], a0, a1, a2, a3, b0, b1);
            }
        }
    }

    const float inv0 = 1.f / l0;
    const float inv1 = 1.f / l1;
    const int row0 = qb * 64 + w * 16 + gi;
    float* y0 = g_y + (size_t)row0 * C_DIM + h * 64;
    float* y1 = y0 + 8 * C_DIM;
#pragma unroll
    for (int n = 0; n < 8; n++) {
        float2 v0, v1;
        v0.x = o[n][0] * inv0; v0.y = o[n][1] * inv0;
        v1.x = o[n][2] * inv1; v1.y = o[n][3] * inv1;
        *(float2*)(y0 + n * 8 + 2 * ti) = v0;
        *(float2*)(y1 + n * 8 + 2 * ti) = v1;
    }
}

// ---------------------------------------------------------------------------
// Launch: cvt(x,Wqkv) -> qkv GEMM -> cvt K/V -> flash -> cvt(y,Wproj) -> proj
// ---------------------------------------------------------------------------
extern "C" void kernel_launch(void* const* d_in, const int* in_sizes, int n_in,
                              void* d_out, int out_size)
{
    (void)in_sizes; (void)n_in; (void)out_size;
    const float* x      = (const float*)d_in[0];
    const float* W_qkv  = (const float*)d_in[2];
    const float* b_qkv  = (const float*)d_in[3];
    const float* W_proj = (const float*)d_in[4];
    const float* b_proj = (const float*)d_in[5];
    float* out = (float*)d_out;

    __half *ah, *al, *bt;
    cudaGetSymbolAddress((void**)&ah, g_ah);
    cudaGetSymbolAddress((void**)&al, g_al);
    cudaGetSymbolAddress((void**)&bt, g_bt);
    float *qkv_out, *y_in;
    cudaGetSymbolAddress((void**)&qkv_out, g_qkv);
    cudaGetSymbolAddress((void**)&y_in, g_y);

    // QKV GEMM operands + GEMM
    k_cvtA<<<T_DIM * C_DIM / 8 / 256, 256>>>(x, ah, al);
    dim3 gw1(F_DIM / 32, C_DIM / 32);
    k_cvtWt<<<gw1, 256>>>(W_qkv, bt, C_DIM, F_DIM);
    dim3 g1(F_DIM / 128, T_DIM / 128);   // (18, 32)
    k_gemm16<<<g1, 256>>>(ah, al, bt, b_qkv, qkv_out, F_DIM, C_DIM);

    // K/V fp16 pre-convert + attention
    k_cvtK<<<1536, 256>>>();
    dim3 gv(T_DIM / 64, H_DIM);
    k_cvtV<<<gv, 256>>>();
    dim3 g2(T_DIM / 64, H_DIM);          // (64, 12)
    k_flash<<<g2, 128>>>();

    // Proj GEMM operands + GEMM
    k_cvtA<<<T_DIM * C_DIM / 8 / 256, 256>>>(y_in, ah, al);
    dim3 gw2(C_DIM / 32, C_DIM / 32);
    k_cvtWt<<<gw2, 256>>>(W_proj, bt, C_DIM, C_DIM);
    dim3 g3(C_DIM / 128, T_DIM / 128);   // (6, 32)
    k_gemm16<<<g3, 256>>>(ah, al, bt, b_proj, out, C_DIM, C_DIM);
}

// round 11
// speedup vs baseline: 7.0708x; 1.1101x over previous
#include <cuda_runtime.h>
#include <cuda_fp16.h>

#define T_DIM 4096
#define C_DIM 768
#define H_DIM 12
#define D_DIM 64
#define F_DIM 2304   // 3*C

// Scratch (allocation-free: __device__ globals)
__device__ float  g_qkv[T_DIM * F_DIM];          // [t][f] Q|K|V fp32
__device__ float  g_y[T_DIM * C_DIM];            // attention output
__device__ __half g_k16[H_DIM * T_DIM * D_DIM];  // K fp16 [h][t][d]
__device__ __half g_v16t[H_DIM * D_DIM * T_DIM]; // V fp16 transposed [h][d][t]
__device__ __half g_ah[T_DIM * C_DIM];           // GEMM A hi fp16 [m][k]
__device__ __half g_al[T_DIM * C_DIM];           // GEMM A lo fp16 [m][k]
__device__ __half g_bt[C_DIM * F_DIM];           // GEMM B^T fp16 [n][k]

#define QSCALE 0.18033688011112042f   // 0.125 * log2(e)

// ---------------------------------------------------------------------------
// helpers
// ---------------------------------------------------------------------------
__device__ __forceinline__ unsigned h2_as_u32(__half2 v) {
    unsigned u;
    memcpy(&u, &v, 4);
    return u;
}

__device__ __forceinline__ void mma_f16(float& c0, float& c1, float& c2, float& c3,
                                        unsigned a0, unsigned a1, unsigned a2, unsigned a3,
                                        unsigned b0, unsigned b1)
{
    asm volatile("mma.sync.aligned.m16n8k16.row.col.f32.f16.f16.f32 "
                 "{%0,%1,%2,%3},{%4,%5,%6,%7},{%8,%9},{%0,%1,%2,%3};"
                 : "+f"(c0), "+f"(c1), "+f"(c2), "+f"(c3)
                 : "r"(a0), "r"(a1), "r"(a2), "r"(a3), "r"(b0), "r"(b1));
}

__device__ __forceinline__ void cp_async16(void* smem_dst, const void* gmem_src)
{
    unsigned dst = (unsigned)__cvta_generic_to_shared(smem_dst);
    asm volatile("cp.async.cg.shared.global [%0], [%1], 16;" :: "r"(dst), "l"(gmem_src));
}

// ---------------------------------------------------------------------------
// Operand pre-conversion kernels
// ---------------------------------------------------------------------------
__global__ __launch_bounds__(256) void k_cvtA(const float* __restrict__ src,
                                              __half* __restrict__ dh,
                                              __half* __restrict__ dl)
{
    const size_t i8 = ((size_t)blockIdx.x * 256 + threadIdx.x) * 8;
    float4 a = *(const float4*)(src + i8);
    float4 b = *(const float4*)(src + i8 + 4);
    float v[8] = {a.x, a.y, a.z, a.w, b.x, b.y, b.z, b.w};
    __half hs[8], ls[8];
#pragma unroll
    for (int e = 0; e < 8; e++) {
        __half hi = __float2half_rn(v[e]);
        hs[e] = hi;
        ls[e] = __float2half_rn(v[e] - __half2float(hi));
    }
    uint4 oh, ol;
    oh.x = h2_as_u32(__halves2half2(hs[0], hs[1]));
    oh.y = h2_as_u32(__halves2half2(hs[2], hs[3]));
    oh.z = h2_as_u32(__halves2half2(hs[4], hs[5]));
    oh.w = h2_as_u32(__halves2half2(hs[6], hs[7]));
    ol.x = h2_as_u32(__halves2half2(ls[0], ls[1]));
    ol.y = h2_as_u32(__halves2half2(ls[2], ls[3]));
    ol.z = h2_as_u32(__halves2half2(ls[4], ls[5]));
    ol.w = h2_as_u32(__halves2half2(ls[6], ls[7]));
    *(uint4*)(&dh[i8]) = oh;
    *(uint4*)(&dl[i8]) = ol;
}

__global__ __launch_bounds__(256) void k_cvtWt(const float* __restrict__ W,
                                               __half* __restrict__ Wt,
                                               int K, int N)
{
    __shared__ __half S[32][33];
    const int tx = threadIdx.x & 31;
    const int ty = threadIdx.x >> 5;
    const int n0 = blockIdx.x * 32;
    const int k0 = blockIdx.y * 32;
#pragma unroll
    for (int e = 0; e < 4; e++)
        S[ty + 8 * e][tx] = __float2half_rn(W[(size_t)(k0 + ty + 8 * e) * N + n0 + tx]);
    __syncthreads();
#pragma unroll
    for (int e = 0; e < 4; e++)
        Wt[(size_t)(n0 + ty + 8 * e) * K + k0 + tx] = S[tx][ty + 8 * e];
}

// ---------------------------------------------------------------------------
// fp16 hi/lo tensor-core GEMM (unchanged from round 9)
// ---------------------------------------------------------------------------
__global__ __launch_bounds__(256, 2) void k_gemm16(const __half* __restrict__ Ahg,
                                                   const __half* __restrict__ Alg,
                                                   const __half* __restrict__ Btg,
                                                   const float* __restrict__ bias,
                                                   float* __restrict__ Cc,
                                                   int N, int K)
{
    __shared__ __align__(16) __half Ah[2][128][24];
    __shared__ __align__(16) __half Al[2][128][24];
    __shared__ __align__(16) __half Bs[2][128][24];

    const int tid  = threadIdx.x;
    const int bx   = blockIdx.x, by = blockIdx.y;
    const int w    = tid >> 5;
    const int lane = tid & 31;
    const int gi   = lane >> 2;
    const int ti   = lane & 3;
    const int wm   = (w & 1) * 64;
    const int wn   = (w >> 1) * 32;

    const int frow = tid >> 1;
    const int fofs = (tid & 1) * 8;

    const __half* aSrcH = Ahg + (size_t)(by * 128 + frow) * K + fofs;
    const __half* aSrcL = Alg + (size_t)(by * 128 + frow) * K + fofs;
    const __half* bSrc  = Btg + (size_t)(bx * 128 + frow) * K + fofs;

    auto produce = [&](int stage) {
        const int buf = stage & 1;
        const int k0 = stage * 16;
        cp_async16(&Ah[buf][frow][fofs], aSrcH + k0);
        cp_async16(&Al[buf][frow][fofs], aSrcL + k0);
        cp_async16(&Bs[buf][frow][fofs], bSrc + k0);
        asm volatile("cp.async.commit_group;" ::: "memory");
    };

    float acc[4][4][4];
#pragma unroll
    for (int i = 0; i < 4; i++)
#pragma unroll
        for (int j = 0; j < 4; j++)
#pragma unroll
            for (int c = 0; c < 4; c++) acc[i][j][c] = 0.f;

    const int NS = K / 16;
    produce(0);

    for (int s = 0; s < NS; s++) {
        if (s + 1 < NS) {
            produce(s + 1);
            asm volatile("cp.async.wait_group 1;" ::: "memory");
        } else {
            asm volatile("cp.async.wait_group 0;" ::: "memory");
        }
        __syncthreads();
        const int buf = s & 1;

        unsigned bf[4][2];
#pragma unroll
        for (int nf = 0; nf < 4; nf++) {
            const int n0 = wn + nf * 8 + gi;
            bf[nf][0] = *(const unsigned*)(&Bs[buf][n0][2 * ti]);
            bf[nf][1] = *(const unsigned*)(&Bs[buf][n0][2 * ti + 8]);
        }
        unsigned ah[4][4], alr[4][4];
#pragma unroll
        for (int mf = 0; mf < 4; mf++) {
            const int m0 = wm + mf * 16 + gi;
            ah[mf][0]  = *(const unsigned*)(&Ah[buf][m0][2 * ti]);
            ah[mf][1]  = *(const unsigned*)(&Ah[buf][m0 + 8][2 * ti]);
            ah[mf][2]  = *(const unsigned*)(&Ah[buf][m0][2 * ti + 8]);
            ah[mf][3]  = *(const unsigned*)(&Ah[buf][m0 + 8][2 * ti + 8]);
            alr[mf][0] = *(const unsigned*)(&Al[buf][m0][2 * ti]);
            alr[mf][1] = *(const unsigned*)(&Al[buf][m0 + 8][2 * ti]);
            alr[mf][2] = *(const unsigned*)(&Al[buf][m0][2 * ti + 8]);
            alr[mf][3] = *(const unsigned*)(&Al[buf][m0 + 8][2 * ti + 8]);
        }
#pragma unroll
        for (int mf = 0; mf < 4; mf++)
#pragma unroll
            for (int nf = 0; nf < 4; nf++) {
                mma_f16(acc[mf][nf][0], acc[mf][nf][1], acc[mf][nf][2], acc[mf][nf][3],
                        ah[mf][0], ah[mf][1], ah[mf][2], ah[mf][3],
                        bf[nf][0], bf[nf][1]);
                mma_f16(acc[mf][nf][0], acc[mf][nf][1], acc[mf][nf][2], acc[mf][nf][3],
                        alr[mf][0], alr[mf][1], alr[mf][2], alr[mf][3],
                        bf[nf][0], bf[nf][1]);
            }
        __syncthreads();
    }

#pragma unroll
    for (int mf = 0; mf < 4; mf++) {
        const int row = by * 128 + wm + mf * 16 + gi;
#pragma unroll
        for (int nf = 0; nf < 4; nf++) {
            const int col = bx * 128 + wn + nf * 8 + 2 * ti;
            const float bv0 = bias[col], bv1 = bias[col + 1];
            float2 v0, v1;
            v0.x = acc[mf][nf][0] + bv0; v0.y = acc[mf][nf][1] + bv1;
            v1.x = acc[mf][nf][2] + bv0; v1.y = acc[mf][nf][3] + bv1;
            *(float2*)(&Cc[(size_t)row * N + col])       = v0;
            *(float2*)(&Cc[(size_t)(row + 8) * N + col]) = v1;
        }
    }
}

// ---------------------------------------------------------------------------
// Pre-convert K -> fp16 [h][t][d]
// ---------------------------------------------------------------------------
__global__ __launch_bounds__(256) void k_cvtK()
{
    const int idx = blockIdx.x * 256 + threadIdx.x;
    const int flat8 = idx * 8;
    const int h = flat8 >> 18;
    const int rem = flat8 & 262143;
    const int t = rem >> 6;
    const int d = rem & 63;
    const float* src = g_qkv + (size_t)t * F_DIM + C_DIM + h * 64 + d;
    float4 a = *(const float4*)(src);
    float4 b = *(const float4*)(src + 4);
    uint4 o;
    o.x = h2_as_u32(__floats2half2_rn(a.x, a.y));
    o.y = h2_as_u32(__floats2half2_rn(a.z, a.w));
    o.z = h2_as_u32(__floats2half2_rn(b.x, b.y));
    o.w = h2_as_u32(__floats2half2_rn(b.z, b.w));
    *(uint4*)(&g_k16[flat8]) = o;
}

// ---------------------------------------------------------------------------
// Pre-convert V -> fp16 transposed [h][d][t]
// ---------------------------------------------------------------------------
__global__ __launch_bounds__(256) void k_cvtV()
{
    __shared__ __half S[64][72];
    const int tid = threadIdx.x;
    const int t0  = blockIdx.x * 64;
    const int h   = blockIdx.y;
    {
        const int tr = tid >> 2;
        const int dp = (tid & 3) << 4;
        const float* src = g_qkv + (size_t)(t0 + tr) * F_DIM + 2 * C_DIM + h * 64 + dp;
#pragma unroll
        for (int e = 0; e < 4; e++) {
            float4 v = *(const float4*)(src + 4 * e);
            __half2 p0 = __floats2half2_rn(v.x, v.y);
            __half2 p1 = __floats2half2_rn(v.z, v.w);
            *(__half2*)(&S[tr][dp + 4 * e])     = p0;
            *(__half2*)(&S[tr][dp + 4 * e + 2]) = p1;
        }
    }
    __syncthreads();
    {
        const int d  = tid >> 2;
        const int tp = (tid & 3) << 4;
        __half* dst = g_v16t + ((size_t)h * 64 + d) * T_DIM + t0 + tp;
#pragma unroll
        for (int e = 0; e < 8; e++) {
            __half2 v = __halves2half2(S[tp + 2 * e][d], S[tp + 2 * e + 1][d]);
            *(__half2*)(dst + 2 * e) = v;
        }
    }
}

// ---------------------------------------------------------------------------
// Flash attention body for ONE 64-row q-block (fp16 m16n8k16, double-buffered
// cp.async, exp2-domain softmax). Called twice per CTA with paired qb values
// so every CTA does exactly 65 tiles of work (perfect causal load balance).
// ---------------------------------------------------------------------------
__device__ __forceinline__ void flash_body(int qb, int h,
                                           __half (*Ks)[64][72],
                                           __half (*Vt)[64][72])
{
    const int tid  = threadIdx.x;
    const int w    = tid >> 5;
    const int lane = tid & 31;
    const int gi   = lane >> 2;
    const int ti   = lane & 3;

    // Q A-fragments (fp16), scaled by 0.125*log2(e) -> exp2 softmax domain
    unsigned qa[4][4];
    {
        const float* q0 = g_qkv + (size_t)(qb * 64 + w * 16 + gi) * F_DIM + h * 64;
        const float* q1 = q0 + 8 * F_DIM;
#pragma unroll
        for (int kc = 0; kc < 4; kc++) {
            const int c0 = kc * 16 + 2 * ti;
            qa[kc][0] = h2_as_u32(__floats2half2_rn(q0[c0] * QSCALE,     q0[c0 + 1] * QSCALE));
            qa[kc][1] = h2_as_u32(__floats2half2_rn(q1[c0] * QSCALE,     q1[c0 + 1] * QSCALE));
            qa[kc][2] = h2_as_u32(__floats2half2_rn(q0[c0 + 8] * QSCALE, q0[c0 + 9] * QSCALE));
            qa[kc][3] = h2_as_u32(__floats2half2_rn(q1[c0 + 8] * QSCALE, q1[c0 + 9] * QSCALE));
        }
    }

    float o[8][4];
#pragma unroll
    for (int n = 0; n < 8; n++) { o[n][0] = o[n][1] = o[n][2] = o[n][3] = 0.f; }
    float m0 = -1e30f, m1 = -1e30f, l0 = 0.f, l1 = 0.f;

    const __half* kbase = g_k16 + (size_t)h * T_DIM * 64;
    const __half* vbase = g_v16t + (size_t)h * 64 * T_DIM;
    const int frow = tid >> 1;
    const int fcol = (tid & 1) * 32;

    auto produce = [&](int j, int buf) {
        const __half* ksrc = kbase + (size_t)(j * 64 + frow) * 64 + fcol;
        __half* kdst = &Ks[buf][frow][fcol];
#pragma unroll
        for (int e = 0; e < 4; e++) cp_async16(kdst + 8 * e, ksrc + 8 * e);
        const __half* vsrc = vbase + (size_t)frow * T_DIM + j * 64 + fcol;
        __half* vdst = &Vt[buf][frow][fcol];
#pragma unroll
        for (int e = 0; e < 4; e++) cp_async16(vdst + 8 * e, vsrc + 8 * e);
        asm volatile("cp.async.commit_group;" ::: "memory");
    };

    __syncthreads();   // previous body's last-tile reads complete before refill
    produce(0, 0);

    for (int j = 0; j <= qb; j++) {
        asm volatile("cp.async.wait_group 0;" ::: "memory");
        __syncthreads();
        if (j < qb) produce(j + 1, (j + 1) & 1);
        const int buf = j & 1;

        float s[8][4];
#pragma unroll
        for (int n = 0; n < 8; n++) { s[n][0] = s[n][1] = s[n][2] = s[n][3] = 0.f; }
#pragma unroll
        for (int kc = 0; kc < 4; kc++) {
#pragma unroll
            for (int n = 0; n < 8; n++) {
                unsigned b0 = *(const unsigned*)(&Ks[buf][n * 8 + gi][kc * 16 + 2 * ti]);
                unsigned b1 = *(const unsigned*)(&Ks[buf][n * 8 + gi][kc * 16 + 2 * ti + 8]);
                mma_f16(s[n][0], s[n][1], s[n][2], s[n][3],
                        qa[kc][0], qa[kc][1], qa[kc][2], qa[kc][3], b0, b1);
            }
        }

        if (j == qb) {
            const int r0l = w * 16 + gi;
            const int r1l = r0l + 8;
#pragma unroll
            for (int n = 0; n < 8; n++) {
                const int col = n * 8 + 2 * ti;
                if (col     > r0l) s[n][0] = -1e30f;
                if (col + 1 > r0l) s[n][1] = -1e30f;
                if (col     > r1l) s[n][2] = -1e30f;
                if (col + 1 > r1l) s[n][3] = -1e30f;
            }
        }

        float rmax0 = -1e30f, rmax1 = -1e30f;
#pragma unroll
        for (int n = 0; n < 8; n++) {
            rmax0 = fmaxf(rmax0, fmaxf(s[n][0], s[n][1]));
            rmax1 = fmaxf(rmax1, fmaxf(s[n][2], s[n][3]));
        }
        rmax0 = fmaxf(rmax0, __shfl_xor_sync(0xffffffffu, rmax0, 1));
        rmax0 = fmaxf(rmax0, __shfl_xor_sync(0xffffffffu, rmax0, 2));
        rmax1 = fmaxf(rmax1, __shfl_xor_sync(0xffffffffu, rmax1, 1));
        rmax1 = fmaxf(rmax1, __shfl_xor_sync(0xffffffffu, rmax1, 2));

        const float mn0 = fmaxf(m0, rmax0);
        const float mn1 = fmaxf(m1, rmax1);
        const float corr0 = exp2f(m0 - mn0);
        const float corr1 = exp2f(m1 - mn1);
        m0 = mn0; m1 = mn1;

        unsigned ph[8][2];
        float sum0 = 0.f, sum1 = 0.f;
#pragma unroll
        for (int n = 0; n < 8; n++) {
            float p00 = exp2f(s[n][0] - mn0);
            float p01 = exp2f(s[n][1] - mn0);
            float p10 = exp2f(s[n][2] - mn1);
            float p11 = exp2f(s[n][3] - mn1);
            sum0 += p00 + p01;
            sum1 += p10 + p11;
            ph[n][0] = h2_as_u32(__floats2half2_rn(p00, p01));
            ph[n][1] = h2_as_u32(__floats2half2_rn(p10, p11));
        }
        sum0 += __shfl_xor_sync(0xffffffffu, sum0, 1);
        sum0 += __shfl_xor_sync(0xffffffffu, sum0, 2);
        sum1 += __shfl_xor_sync(0xffffffffu, sum1, 1);
        sum1 += __shfl_xor_sync(0xffffffffu, sum1, 2);
        l0 = l0 * corr0 + sum0;
        l1 = l1 * corr1 + sum1;

#pragma unroll
        for (int n = 0; n < 8; n++) {
            o[n][0] *= corr0; o[n][1] *= corr0;
            o[n][2] *= corr1; o[n][3] *= corr1;
        }

#pragma unroll
        for (int kc = 0; kc < 4; kc++) {
            unsigned a0 = ph[2 * kc][0];
            unsigned a1 = ph[2 * kc][1];
            unsigned a2 = ph[2 * kc + 1][0];
            unsigned a3 = ph[2 * kc + 1][1];
#pragma unroll
            for (int n = 0; n < 8; n++) {
                unsigned b0 = *(const unsigned*)(&Vt[buf][n * 8 + gi][kc * 16 + 2 * ti]);
                unsigned b1 = *(const unsigned*)(&Vt[buf][n * 8 + gi][kc * 16 + 2 * ti + 8]);
                mma_f16(o[n][0], o[n][1], o[n][2], o[n][3], a0, a1, a2, a3, b0, b1);
            }
        }
    }

    const float inv0 = 1.f / l0;
    const float inv1 = 1.f / l1;
    const int row0 = qb * 64 + w * 16 + gi;
    float* y0 = g_y + (size_t)row0 * C_DIM + h * 64;
    float* y1 = y0 + 8 * C_DIM;
#pragma unroll
    for (int n = 0; n < 8; n++) {
        float2 v0, v1;
        v0.x = o[n][0] * inv0; v0.y = o[n][1] * inv0;
        v1.x = o[n][2] * inv1; v1.y = o[n][3] * inv1;
        *(float2*)(y0 + n * 8 + 2 * ti) = v0;
        *(float2*)(y1 + n * 8 + 2 * ti) = v1;
    }
}

// CTA x handles q-blocks (63-x) and x: constant 65 tiles of work per CTA.
__global__ __launch_bounds__(128) void k_flash()
{
    __shared__ __align__(16) __half Ks[2][64][72];
    __shared__ __align__(16) __half Vt[2][64][72];
    const int x = blockIdx.x;      // 0..31
    const int h = blockIdx.y;
    flash_body(63 - x, h, Ks, Vt);
    flash_body(x,      h, Ks, Vt);
}

// ---------------------------------------------------------------------------
// Launch: cvt(x,Wqkv) -> qkv GEMM -> cvt K/V -> flash -> cvt(y,Wproj) -> proj
// ---------------------------------------------------------------------------
extern "C" void kernel_launch(void* const* d_in, const int* in_sizes, int n_in,
                              void* d_out, int out_size)
{
    (void)in_sizes; (void)n_in; (void)out_size;
    const float* x      = (const float*)d_in[0];
    const float* W_qkv  = (const float*)d_in[2];
    const float* b_qkv  = (const float*)d_in[3];
    const float* W_proj = (const float*)d_in[4];
    const float* b_proj = (const float*)d_in[5];
    float* out = (float*)d_out;

    __half *ah, *al, *bt;
    cudaGetSymbolAddress((void**)&ah, g_ah);
    cudaGetSymbolAddress((void**)&al, g_al);
    cudaGetSymbolAddress((void**)&bt, g_bt);
    float *qkv_out, *y_in;
    cudaGetSymbolAddress((void**)&qkv_out, g_qkv);
    cudaGetSymbolAddress((void**)&y_in, g_y);

    // QKV GEMM operands + GEMM
    k_cvtA<<<T_DIM * C_DIM / 8 / 256, 256>>>(x, ah, al);
    dim3 gw1(F_DIM / 32, C_DIM / 32);
    k_cvtWt<<<gw1, 256>>>(W_qkv, bt, C_DIM, F_DIM);
    dim3 g1(F_DIM / 128, T_DIM / 128);   // (18, 32)
    k_gemm16<<<g1, 256>>>(ah, al, bt, b_qkv, qkv_out, F_DIM, C_DIM);

    // K/V fp16 pre-convert + attention (paired causal balance)
    k_cvtK<<<1536, 256>>>();
    dim3 gv(T_DIM / 64, H_DIM);
    k_cvtV<<<gv, 256>>>();
    dim3 g2(T_DIM / 128, H_DIM);         // (32, 12)
    k_flash<<<g2, 128>>>();

    // Proj GEMM operands + GEMM
    k_cvtA<<<T_DIM * C_DIM / 8 / 256, 256>>>(y_in, ah, al);
    dim3 gw2(C_DIM / 32, C_DIM / 32);
    k_cvtWt<<<gw2, 256>>>(W_proj, bt, C_DIM, C_DIM);
    dim3 g3(C_DIM / 128, T_DIM / 128);   // (6, 32)
    k_gemm16<<<g3, 256>>>(ah, al, bt, b_proj, out, C_DIM, C_DIM);
}

// round 15
// speedup vs baseline: 7.5398x; 1.0663x over previous
#include <cuda_runtime.h>
#include <cuda_fp16.h>

#define T_DIM 4096
#define C_DIM 768
#define H_DIM 12
#define D_DIM 64
#define F_DIM 2304   // 3*C

// Scratch (allocation-free: __device__ globals)
__device__ float  g_qkv[T_DIM * F_DIM];          // [t][f] Q|K|V fp32
__device__ float  g_y[T_DIM * C_DIM];            // attention output
__device__ __half g_k16[H_DIM * T_DIM * D_DIM];  // K fp16 [h][t][d]
__device__ __half g_v16t[H_DIM * D_DIM * T_DIM]; // V fp16 transposed [h][d][t]
__device__ __half g_ah[T_DIM * C_DIM];           // GEMM A hi fp16 [m][k]
__device__ __half g_al[T_DIM * C_DIM];           // GEMM A lo fp16 [m][k]
__device__ __half g_bt[C_DIM * F_DIM];           // GEMM B^T fp16 [n][k]

#define QSCALE 0.18033688011112042f   // 0.125 * log2(e)

// ---------------------------------------------------------------------------
// helpers
// ---------------------------------------------------------------------------
__device__ __forceinline__ unsigned h2_as_u32(__half2 v) {
    unsigned u;
    memcpy(&u, &v, 4);
    return u;
}

__device__ __forceinline__ void mma_f16(float& c0, float& c1, float& c2, float& c3,
                                        unsigned a0, unsigned a1, unsigned a2, unsigned a3,
                                        unsigned b0, unsigned b1)
{
    asm volatile("mma.sync.aligned.m16n8k16.row.col.f32.f16.f16.f32 "
                 "{%0,%1,%2,%3},{%4,%5,%6,%7},{%8,%9},{%0,%1,%2,%3};"
                 : "+f"(c0), "+f"(c1), "+f"(c2), "+f"(c3)
                 : "r"(a0), "r"(a1), "r"(a2), "r"(a3), "r"(b0), "r"(b1));
}

__device__ __forceinline__ void cp_async16(void* smem_dst, const void* gmem_src)
{
    unsigned dst = (unsigned)__cvta_generic_to_shared(smem_dst);
    asm volatile("cp.async.cg.shared.global [%0], [%1], 16;" :: "r"(dst), "l"(gmem_src));
}

// ---------------------------------------------------------------------------
// Operand pre-conversion kernels
// ---------------------------------------------------------------------------
__global__ __launch_bounds__(256) void k_cvtA(const float* __restrict__ src,
                                              __half* __restrict__ dh,
                                              __half* __restrict__ dl)
{
    const size_t i8 = ((size_t)blockIdx.x * 256 + threadIdx.x) * 8;
    float4 a = *(const float4*)(src + i8);
    float4 b = *(const float4*)(src + i8 + 4);
    float v[8] = {a.x, a.y, a.z, a.w, b.x, b.y, b.z, b.w};
    __half hs[8], ls[8];
#pragma unroll
    for (int e = 0; e < 8; e++) {
        __half hi = __float2half_rn(v[e]);
        hs[e] = hi;
        ls[e] = __float2half_rn(v[e] - __half2float(hi));
    }
    uint4 oh, ol;
    oh.x = h2_as_u32(__halves2half2(hs[0], hs[1]));
    oh.y = h2_as_u32(__halves2half2(hs[2], hs[3]));
    oh.z = h2_as_u32(__halves2half2(hs[4], hs[5]));
    oh.w = h2_as_u32(__halves2half2(hs[6], hs[7]));
    ol.x = h2_as_u32(__halves2half2(ls[0], ls[1]));
    ol.y = h2_as_u32(__halves2half2(ls[2], ls[3]));
    ol.z = h2_as_u32(__halves2half2(ls[4], ls[5]));
    ol.w = h2_as_u32(__halves2half2(ls[6], ls[7]));
    *(uint4*)(&dh[i8]) = oh;
    *(uint4*)(&dl[i8]) = ol;
}

__global__ __launch_bounds__(256) void k_cvtWt(const float* __restrict__ W,
                                               __half* __restrict__ Wt,
                                               int K, int N)
{
    __shared__ __half S[32][33];
    const int tx = threadIdx.x & 31;
    const int ty = threadIdx.x >> 5;
    const int n0 = blockIdx.x * 32;
    const int k0 = blockIdx.y * 32;
#pragma unroll
    for (int e = 0; e < 4; e++)
        S[ty + 8 * e][tx] = __float2half_rn(W[(size_t)(k0 + ty + 8 * e) * N + n0 + tx]);
    __syncthreads();
#pragma unroll
    for (int e = 0; e < 4; e++)
        Wt[(size_t)(n0 + ty + 8 * e) * K + k0 + tx] = S[tx][ty + 8 * e];
}

// ---------------------------------------------------------------------------
// fp16 hi/lo tensor-core GEMM (unchanged)
// ---------------------------------------------------------------------------
__global__ __launch_bounds__(256, 2) void k_gemm16(const __half* __restrict__ Ahg,
                                                   const __half* __restrict__ Alg,
                                                   const __half* __restrict__ Btg,
                                                   const float* __restrict__ bias,
                                                   float* __restrict__ Cc,
                                                   int N, int K)
{
    __shared__ __align__(16) __half Ah[2][128][24];
    __shared__ __align__(16) __half Al[2][128][24];
    __shared__ __align__(16) __half Bs[2][128][24];

    const int tid  = threadIdx.x;
    const int bx   = blockIdx.x, by = blockIdx.y;
    const int w    = tid >> 5;
    const int lane = tid & 31;
    const int gi   = lane >> 2;
    const int ti   = lane & 3;
    const int wm   = (w & 1) * 64;
    const int wn   = (w >> 1) * 32;

    const int frow = tid >> 1;
    const int fofs = (tid & 1) * 8;

    const __half* aSrcH = Ahg + (size_t)(by * 128 + frow) * K + fofs;
    const __half* aSrcL = Alg + (size_t)(by * 128 + frow) * K + fofs;
    const __half* bSrc  = Btg + (size_t)(bx * 128 + frow) * K + fofs;

    auto produce = [&](int stage) {
        const int buf = stage & 1;
        const int k0 = stage * 16;
        cp_async16(&Ah[buf][frow][fofs], aSrcH + k0);
        cp_async16(&Al[buf][frow][fofs], aSrcL + k0);
        cp_async16(&Bs[buf][frow][fofs], bSrc + k0);
        asm volatile("cp.async.commit_group;" ::: "memory");
    };

    float acc[4][4][4];
#pragma unroll
    for (int i = 0; i < 4; i++)
#pragma unroll
        for (int j = 0; j < 4; j++)
#pragma unroll
            for (int c = 0; c < 4; c++) acc[i][j][c] = 0.f;

    const int NS = K / 16;
    produce(0);

    for (int s = 0; s < NS; s++) {
        if (s + 1 < NS) {
            produce(s + 1);
            asm volatile("cp.async.wait_group 1;" ::: "memory");
        } else {
            asm volatile("cp.async.wait_group 0;" ::: "memory");
        }
        __syncthreads();
        const int buf = s & 1;

        unsigned bf[4][2];
#pragma unroll
        for (int nf = 0; nf < 4; nf++) {
            const int n0 = wn + nf * 8 + gi;
            bf[nf][0] = *(const unsigned*)(&Bs[buf][n0][2 * ti]);
            bf[nf][1] = *(const unsigned*)(&Bs[buf][n0][2 * ti + 8]);
        }
        unsigned ah[4][4], alr[4][4];
#pragma unroll
        for (int mf = 0; mf < 4; mf++) {
            const int m0 = wm + mf * 16 + gi;
            ah[mf][0]  = *(const unsigned*)(&Ah[buf][m0][2 * ti]);
            ah[mf][1]  = *(const unsigned*)(&Ah[buf][m0 + 8][2 * ti]);
            ah[mf][2]  = *(const unsigned*)(&Ah[buf][m0][2 * ti + 8]);
            ah[mf][3]  = *(const unsigned*)(&Ah[buf][m0 + 8][2 * ti + 8]);
            alr[mf][0] = *(const unsigned*)(&Al[buf][m0][2 * ti]);
            alr[mf][1] = *(const unsigned*)(&Al[buf][m0 + 8][2 * ti]);
            alr[mf][2] = *(const unsigned*)(&Al[buf][m0][2 * ti + 8]);
            alr[mf][3] = *(const unsigned*)(&Al[buf][m0 + 8][2 * ti + 8]);
        }
#pragma unroll
        for (int mf = 0; mf < 4; mf++)
#pragma unroll
            for (int nf = 0; nf < 4; nf++) {
                mma_f16(acc[mf][nf][0], acc[mf][nf][1], acc[mf][nf][2], acc[mf][nf][3],
                        ah[mf][0], ah[mf][1], ah[mf][2], ah[mf][3],
                        bf[nf][0], bf[nf][1]);
                mma_f16(acc[mf][nf][0], acc[mf][nf][1], acc[mf][nf][2], acc[mf][nf][3],
                        alr[mf][0], alr[mf][1], alr[mf][2], alr[mf][3],
                        bf[nf][0], bf[nf][1]);
            }
        __syncthreads();
    }

#pragma unroll
    for (int mf = 0; mf < 4; mf++) {
        const int row = by * 128 + wm + mf * 16 + gi;
#pragma unroll
        for (int nf = 0; nf < 4; nf++) {
            const int col = bx * 128 + wn + nf * 8 + 2 * ti;
            const float bv0 = bias[col], bv1 = bias[col + 1];
            float2 v0, v1;
            v0.x = acc[mf][nf][0] + bv0; v0.y = acc[mf][nf][1] + bv1;
            v1.x = acc[mf][nf][2] + bv0; v1.y = acc[mf][nf][3] + bv1;
            *(float2*)(&Cc[(size_t)row * N + col])       = v0;
            *(float2*)(&Cc[(size_t)(row + 8) * N + col]) = v1;
        }
    }
}

// ---------------------------------------------------------------------------
// Pre-convert K -> fp16 [h][t][d]
// ---------------------------------------------------------------------------
__global__ __launch_bounds__(256) void k_cvtK()
{
    const int idx = blockIdx.x * 256 + threadIdx.x;
    const int flat8 = idx * 8;
    const int h = flat8 >> 18;
    const int rem = flat8 & 262143;
    const int t = rem >> 6;
    const int d = rem & 63;
    const float* src = g_qkv + (size_t)t * F_DIM + C_DIM + h * 64 + d;
    float4 a = *(const float4*)(src);
    float4 b = *(const float4*)(src + 4);
    uint4 o;
    o.x = h2_as_u32(__floats2half2_rn(a.x, a.y));
    o.y = h2_as_u32(__floats2half2_rn(a.z, a.w));
    o.z = h2_as_u32(__floats2half2_rn(b.x, b.y));
    o.w = h2_as_u32(__floats2half2_rn(b.z, b.w));
    *(uint4*)(&g_k16[flat8]) = o;
}

// ---------------------------------------------------------------------------
// Pre-convert V -> fp16 transposed [h][d][t]
// ---------------------------------------------------------------------------
__global__ __launch_bounds__(256) void k_cvtV()
{
    __shared__ __half S[64][72];
    const int tid = threadIdx.x;
    const int t0  = blockIdx.x * 64;
    const int h   = blockIdx.y;
    {
        const int tr = tid >> 2;
        const int dp = (tid & 3) << 4;
        const float* src = g_qkv + (size_t)(t0 + tr) * F_DIM + 2 * C_DIM + h * 64 + dp;
#pragma unroll
        for (int e = 0; e < 4; e++) {
            float4 v = *(const float4*)(src + 4 * e);
            __half2 p0 = __floats2half2_rn(v.x, v.y);
            __half2 p1 = __floats2half2_rn(v.z, v.w);
            *(__half2*)(&S[tr][dp + 4 * e])     = p0;
            *(__half2*)(&S[tr][dp + 4 * e + 2]) = p1;
        }
    }
    __syncthreads();
    {
        const int d  = tid >> 2;
        const int tp = (tid & 3) << 4;
        __half* dst = g_v16t + ((size_t)h * 64 + d) * T_DIM + t0 + tp;
#pragma unroll
        for (int e = 0; e < 8; e++) {
            __half2 v = __halves2half2(S[tp + 2 * e][d], S[tp + 2 * e + 1][d]);
            *(__half2*)(dst + 2 * e) = v;
        }
    }
}

// ---------------------------------------------------------------------------
// Causal flash attention, fp16 mma, CONCURRENT paired q-blocks.
// CTA x (256 thr, 8 warps): warpgroup 0 -> q-block 63-x, warpgroup 1 -> x.
// One shared K/V tile stream j = 0..63-x; wg1 skips compute for j > x.
// Doubles warps/SMSP vs sequential pairing; halves smem fill traffic.
// ---------------------------------------------------------------------------
__global__ __launch_bounds__(256) void k_flash()
{
    __shared__ __align__(16) __half Ks[2][64][72];   // [buf][key][d]
    __shared__ __align__(16) __half Vt[2][64][72];   // [buf][d][key]

    const int x    = blockIdx.x;          // 0..31
    const int h    = blockIdx.y;
    const int tid  = threadIdx.x;
    const int wg   = tid >> 7;            // warpgroup 0/1
    const int wtid = tid & 127;
    const int w    = wtid >> 5;           // warp within group 0..3
    const int lane = tid & 31;
    const int gi   = lane >> 2;
    const int ti   = lane & 3;

    const int qb   = wg ? x : (63 - x);   // this warpgroup's q-block
    const int jmax = 63 - x;              // tiles to stream

    // Q A-fragments (fp16), scaled into exp2 domain
    unsigned qa[4][4];
    {
        const float* q0 = g_qkv + (size_t)(qb * 64 + w * 16 + gi) * F_DIM + h * 64;
        const float* q1 = q0 + 8 * F_DIM;
#pragma unroll
        for (int kc = 0; kc < 4; kc++) {
            const int c0 = kc * 16 + 2 * ti;
            qa[kc][0] = h2_as_u32(__floats2half2_rn(q0[c0] * QSCALE,     q0[c0 + 1] * QSCALE));
            qa[kc][1] = h2_as_u32(__floats2half2_rn(q1[c0] * QSCALE,     q1[c0 + 1] * QSCALE));
            qa[kc][2] = h2_as_u32(__floats2half2_rn(q0[c0 + 8] * QSCALE, q0[c0 + 9] * QSCALE));
            qa[kc][3] = h2_as_u32(__floats2half2_rn(q1[c0 + 8] * QSCALE, q1[c0 + 9] * QSCALE));
        }
    }

    float o[8][4];
#pragma unroll
    for (int n = 0; n < 8; n++) { o[n][0] = o[n][1] = o[n][2] = o[n][3] = 0.f; }
    float m0 = -1e30f, m1 = -1e30f, l0 = 0.f, l1 = 0.f;

    // tile fill: 256 threads, 4 x 16B cp.async each (2 K + 2 V)
    const __half* kbase = g_k16 + (size_t)h * T_DIM * 64;
    const __half* vbase = g_v16t + (size_t)h * 64 * T_DIM;
    const int frow = tid >> 2;            // 0..63
    const int fcol = (tid & 3) << 4;      // 0,16,32,48

    auto produce = [&](int j, int buf) {
        const __half* ksrc = kbase + (size_t)(j * 64 + frow) * 64 + fcol;
        __half* kdst = &Ks[buf][frow][fcol];
        cp_async16(kdst,     ksrc);
        cp_async16(kdst + 8, ksrc + 8);
        const __half* vsrc = vbase + (size_t)frow * T_DIM + j * 64 + fcol;
        __half* vdst = &Vt[buf][frow][fcol];
        cp_async16(vdst,     vsrc);
        cp_async16(vdst + 8, vsrc + 8);
        asm volatile("cp.async.commit_group;" ::: "memory");
    };

    produce(0, 0);

    for (int j = 0; j <= jmax; j++) {
        asm volatile("cp.async.wait_group 0;" ::: "memory");
        __syncthreads();
        if (j < jmax) produce(j + 1, (j + 1) & 1);
        const int buf = j & 1;

        if (j <= qb) {
            // --- S = Q @ K^T ---
            float s[8][4];
#pragma unroll
            for (int n = 0; n < 8; n++) { s[n][0] = s[n][1] = s[n][2] = s[n][3] = 0.f; }
#pragma unroll
            for (int kc = 0; kc < 4; kc++) {
#pragma unroll
                for (int n = 0; n < 8; n++) {
                    unsigned b0 = *(const unsigned*)(&Ks[buf][n * 8 + gi][kc * 16 + 2 * ti]);
                    unsigned b1 = *(const unsigned*)(&Ks[buf][n * 8 + gi][kc * 16 + 2 * ti + 8]);
                    mma_f16(s[n][0], s[n][1], s[n][2], s[n][3],
                            qa[kc][0], qa[kc][1], qa[kc][2], qa[kc][3], b0, b1);
                }
            }

            // --- causal mask (diagonal tile only) ---
            if (j == qb) {
                const int r0l = w * 16 + gi;
                const int r1l = r0l + 8;
#pragma unroll
                for (int n = 0; n < 8; n++) {
                    const int col = n * 8 + 2 * ti;
                    if (col     > r0l) s[n][0] = -1e30f;
                    if (col + 1 > r0l) s[n][1] = -1e30f;
                    if (col     > r1l) s[n][2] = -1e30f;
                    if (col + 1 > r1l) s[n][3] = -1e30f;
                }
            }

            // --- online softmax (exp2 domain) ---
            float rmax0 = -1e30f, rmax1 = -1e30f;
#pragma unroll
            for (int n = 0; n < 8; n++) {
                rmax0 = fmaxf(rmax0, fmaxf(s[n][0], s[n][1]));
                rmax1 = fmaxf(rmax1, fmaxf(s[n][2], s[n][3]));
            }
            rmax0 = fmaxf(rmax0, __shfl_xor_sync(0xffffffffu, rmax0, 1));
            rmax0 = fmaxf(rmax0, __shfl_xor_sync(0xffffffffu, rmax0, 2));
            rmax1 = fmaxf(rmax1, __shfl_xor_sync(0xffffffffu, rmax1, 1));
            rmax1 = fmaxf(rmax1, __shfl_xor_sync(0xffffffffu, rmax1, 2));

            const float mn0 = fmaxf(m0, rmax0);
            const float mn1 = fmaxf(m1, rmax1);
            const float corr0 = exp2f(m0 - mn0);
            const float corr1 = exp2f(m1 - mn1);
            m0 = mn0; m1 = mn1;

            unsigned ph[8][2];
            float sum0 = 0.f, sum1 = 0.f;
#pragma unroll
            for (int n = 0; n < 8; n++) {
                float p00 = exp2f(s[n][0] - mn0);
                float p01 = exp2f(s[n][1] - mn0);
                float p10 = exp2f(s[n][2] - mn1);
                float p11 = exp2f(s[n][3] - mn1);
                sum0 += p00 + p01;
                sum1 += p10 + p11;
                ph[n][0] = h2_as_u32(__floats2half2_rn(p00, p01));
                ph[n][1] = h2_as_u32(__floats2half2_rn(p10, p11));
            }
            sum0 += __shfl_xor_sync(0xffffffffu, sum0, 1);
            sum0 += __shfl_xor_sync(0xffffffffu, sum0, 2);
            sum1 += __shfl_xor_sync(0xffffffffu, sum1, 1);
            sum1 += __shfl_xor_sync(0xffffffffu, sum1, 2);
            l0 = l0 * corr0 + sum0;
            l1 = l1 * corr1 + sum1;

#pragma unroll
            for (int n = 0; n < 8; n++) {
                o[n][0] *= corr0; o[n][1] *= corr0;
                o[n][2] *= corr1; o[n][3] *= corr1;
            }

            // --- O += P @ V (C-layout == A-layout, no shuffles) ---
#pragma unroll
            for (int kc = 0; kc < 4; kc++) {
                unsigned a0 = ph[2 * kc][0];
                unsigned a1 = ph[2 * kc][1];
                unsigned a2 = ph[2 * kc + 1][0];
                unsigned a3 = ph[2 * kc + 1][1];
#pragma unroll
                for (int n = 0; n < 8; n++) {
                    unsigned b0 = *(const unsigned*)(&Vt[buf][n * 8 + gi][kc * 16 + 2 * ti]);
                    unsigned b1 = *(const unsigned*)(&Vt[buf][n * 8 + gi][kc * 16 + 2 * ti + 8]);
                    mma_f16(o[n][0], o[n][1], o[n][2], o[n][3], a0, a1, a2, a3, b0, b1);
                }
            }
        }
        __syncthreads();   // all warps done reading buf before next overwrite
    }

    // --- normalize and write ---
    const float inv0 = 1.f / l0;
    const float inv1 = 1.f / l1;
    const int row0 = qb * 64 + w * 16 + gi;
    float* y0 = g_y + (size_t)row0 * C_DIM + h * 64;
    float* y1 = y0 + 8 * C_DIM;
#pragma unroll
    for (int n = 0; n < 8; n++) {
        float2 v0, v1;
        v0.x = o[n][0] * inv0; v0.y = o[n][1] * inv0;
        v1.x = o[n][2] * inv1; v1.y = o[n][3] * inv1;
        *(float2*)(y0 + n * 8 + 2 * ti) = v0;
        *(float2*)(y1 + n * 8 + 2 * ti) = v1;
    }
}

// ---------------------------------------------------------------------------
// Launch: cvt(x,Wqkv) -> qkv GEMM -> cvt K/V -> flash -> cvt(y,Wproj) -> proj
// ---------------------------------------------------------------------------
extern "C" void kernel_launch(void* const* d_in, const int* in_sizes, int n_in,
                              void* d_out, int out_size)
{
    (void)in_sizes; (void)n_in; (void)out_size;
    const float* x      = (const float*)d_in[0];
    const float* W_qkv  = (const float*)d_in[2];
    const float* b_qkv  = (const float*)d_in[3];
    const float* W_proj = (const float*)d_in[4];
    const float* b_proj = (const float*)d_in[5];
    float* out = (float*)d_out;

    __half *ah, *al, *bt;
    cudaGetSymbolAddress((void**)&ah, g_ah);
    cudaGetSymbolAddress((void**)&al, g_al);
    cudaGetSymbolAddress((void**)&bt, g_bt);
    float *qkv_out, *y_in;
    cudaGetSymbolAddress((void**)&qkv_out, g_qkv);
    cudaGetSymbolAddress((void**)&y_in, g_y);

    // QKV GEMM operands + GEMM
    k_cvtA<<<T_DIM * C_DIM / 8 / 256, 256>>>(x, ah, al);
    dim3 gw1(F_DIM / 32, C_DIM / 32);
    k_cvtWt<<<gw1, 256>>>(W_qkv, bt, C_DIM, F_DIM);
    dim3 g1(F_DIM / 128, T_DIM / 128);   // (18, 32)
    k_gemm16<<<g1, 256>>>(ah, al, bt, b_qkv, qkv_out, F_DIM, C_DIM);

    // K/V fp16 pre-convert + attention (concurrent paired q-blocks)
    k_cvtK<<<1536, 256>>>();
    dim3 gv(T_DIM / 64, H_DIM);
    k_cvtV<<<gv, 256>>>();
    dim3 g2(T_DIM / 128, H_DIM);         // (32, 12)
    k_flash<<<g2, 256>>>();

    // Proj GEMM operands + GEMM
    k_cvtA<<<T_DIM * C_DIM / 8 / 256, 256>>>(y_in, ah, al);
    dim3 gw2(C_DIM / 32, C_DIM / 32);
    k_cvtWt<<<gw2, 256>>>(W_proj, bt, C_DIM, C_DIM);
    dim3 g3(C_DIM / 128, T_DIM / 128);   // (6, 32)
    k_gemm16<<<g3, 256>>>(ah, al, bt, b_proj, out, C_DIM, C_DIM);
}

// round 16
// speedup vs baseline: 9.3438x; 1.2393x over previous
#include <cuda_runtime.h>
#include <cuda_fp16.h>

#define T_DIM 4096
#define C_DIM 768
#define H_DIM 12
#define D_DIM 64
#define F_DIM 2304   // 3*C

// Scratch (allocation-free: __device__ globals)
__device__ float  g_qkv[T_DIM * F_DIM];          // [t][f] Q|K|V fp32
__device__ float  g_y[T_DIM * C_DIM];            // attention output
__device__ __half g_k16[H_DIM * T_DIM * D_DIM];  // K fp16 [h][t][d]
__device__ __half g_v16t[H_DIM * D_DIM * T_DIM]; // V fp16 transposed [h][d][t]
__device__ __half g_ah[T_DIM * C_DIM];           // GEMM A fp16 [m][k]
__device__ __half g_bt[C_DIM * F_DIM];           // GEMM B^T fp16 [n][k]

#define QSCALE 0.18033688011112042f   // 0.125 * log2(e)

// ---------------------------------------------------------------------------
// helpers
// ---------------------------------------------------------------------------
__device__ __forceinline__ unsigned h2_as_u32(__half2 v) {
    unsigned u;
    memcpy(&u, &v, 4);
    return u;
}

__device__ __forceinline__ void mma_f16(float& c0, float& c1, float& c2, float& c3,
                                        unsigned a0, unsigned a1, unsigned a2, unsigned a3,
                                        unsigned b0, unsigned b1)
{
    asm volatile("mma.sync.aligned.m16n8k16.row.col.f32.f16.f16.f32 "
                 "{%0,%1,%2,%3},{%4,%5,%6,%7},{%8,%9},{%0,%1,%2,%3};"
                 : "+f"(c0), "+f"(c1), "+f"(c2), "+f"(c3)
                 : "r"(a0), "r"(a1), "r"(a2), "r"(a3), "r"(b0), "r"(b1));
}

__device__ __forceinline__ void cp_async16(void* smem_dst, const void* gmem_src)
{
    unsigned dst = (unsigned)__cvta_generic_to_shared(smem_dst);
    asm volatile("cp.async.cg.shared.global [%0], [%1], 16;" :: "r"(dst), "l"(gmem_src));
}

// ---------------------------------------------------------------------------
// Operand pre-conversion kernels
// ---------------------------------------------------------------------------
__global__ __launch_bounds__(256) void k_cvtA(const float* __restrict__ src,
                                              __half* __restrict__ dh)
{
    const size_t i8 = ((size_t)blockIdx.x * 256 + threadIdx.x) * 8;
    float4 a = *(const float4*)(src + i8);
    float4 b = *(const float4*)(src + i8 + 4);
    uint4 oh;
    oh.x = h2_as_u32(__floats2half2_rn(a.x, a.y));
    oh.y = h2_as_u32(__floats2half2_rn(a.z, a.w));
    oh.z = h2_as_u32(__floats2half2_rn(b.x, b.y));
    oh.w = h2_as_u32(__floats2half2_rn(b.z, b.w));
    *(uint4*)(&dh[i8]) = oh;
}

__global__ __launch_bounds__(256) void k_cvtWt(const float* __restrict__ W,
                                               __half* __restrict__ Wt,
                                               int K, int N)
{
    __shared__ __half S[32][33];
    const int tx = threadIdx.x & 31;
    const int ty = threadIdx.x >> 5;
    const int n0 = blockIdx.x * 32;
    const int k0 = blockIdx.y * 32;
#pragma unroll
    for (int e = 0; e < 4; e++)
        S[ty + 8 * e][tx] = __float2half_rn(W[(size_t)(k0 + ty + 8 * e) * N + n0 + tx]);
    __syncthreads();
#pragma unroll
    for (int e = 0; e < 4; e++)
        Wt[(size_t)(n0 + ty + 8 * e) * K + k0 + tx] = S[tx][ty + 8 * e];
}

// ---------------------------------------------------------------------------
// fp16 tensor-core GEMM: C = A @ B + bias.
// A fp16 [M][K], B^T fp16 [N][K], C fp32 [M][N]. 256 thr / 8 warps,
// 128x128 tile, 64x32 warp tile, K-tile 16, 4-stage cp.async ring
// (steady-state wait_group 2 hides ~3 stages of gmem latency),
// ONE barrier per stage. Stride-24 rows -> conflict-free u32 frag LDS.
// ---------------------------------------------------------------------------
__global__ __launch_bounds__(256, 2) void k_gemm16(const __half* __restrict__ Ahg,
                                                   const __half* __restrict__ Btg,
                                                   const float* __restrict__ bias,
                                                   float* __restrict__ Cc,
                                                   int N, int K)
{
    __shared__ __align__(16) __half Ah[4][128][24];
    __shared__ __align__(16) __half Bs[4][128][24];

    const int tid  = threadIdx.x;
    const int bx   = blockIdx.x, by = blockIdx.y;
    const int w    = tid >> 5;
    const int lane = tid & 31;
    const int gi   = lane >> 2;
    const int ti   = lane & 3;
    const int wm   = (w & 1) * 64;
    const int wn   = (w >> 1) * 32;

    const int frow = tid >> 1;          // 0..127
    const int fofs = (tid & 1) * 8;     // 0 / 8

    const __half* aSrc = Ahg + (size_t)(by * 128 + frow) * K + fofs;
    const __half* bSrc = Btg + (size_t)(bx * 128 + frow) * K + fofs;

    auto produce = [&](int stage) {
        const int buf = stage & 3;
        const int k0 = stage * 16;
        cp_async16(&Ah[buf][frow][fofs], aSrc + k0);
        cp_async16(&Bs[buf][frow][fofs], bSrc + k0);
        asm volatile("cp.async.commit_group;" ::: "memory");
    };

    float acc[4][4][4];
#pragma unroll
    for (int i = 0; i < 4; i++)
#pragma unroll
        for (int j = 0; j < 4; j++)
#pragma unroll
            for (int c = 0; c < 4; c++) acc[i][j][c] = 0.f;

    const int NS = K / 16;
    produce(0);
    if (NS > 1) produce(1);
    if (NS > 2) produce(2);

    for (int s = 0; s < NS; s++) {
        const int rem = NS - 1 - s;
        if (rem >= 2)      { asm volatile("cp.async.wait_group 2;" ::: "memory"); }
        else if (rem == 1) { asm volatile("cp.async.wait_group 1;" ::: "memory"); }
        else               { asm volatile("cp.async.wait_group 0;" ::: "memory"); }
        __syncthreads();   // stage s visible; all threads done reading buf (s-4)
        if (s + 3 < NS) produce(s + 3);
        const int buf = s & 3;

        unsigned bf[4][2];
#pragma unroll
        for (int nf = 0; nf < 4; nf++) {
            const int n0 = wn + nf * 8 + gi;
            bf[nf][0] = *(const unsigned*)(&Bs[buf][n0][2 * ti]);
            bf[nf][1] = *(const unsigned*)(&Bs[buf][n0][2 * ti + 8]);
        }
        unsigned ah[4][4];
#pragma unroll
        for (int mf = 0; mf < 4; mf++) {
            const int m0 = wm + mf * 16 + gi;
            ah[mf][0] = *(const unsigned*)(&Ah[buf][m0][2 * ti]);
            ah[mf][1] = *(const unsigned*)(&Ah[buf][m0 + 8][2 * ti]);
            ah[mf][2] = *(const unsigned*)(&Ah[buf][m0][2 * ti + 8]);
            ah[mf][3] = *(const unsigned*)(&Ah[buf][m0 + 8][2 * ti + 8]);
        }
#pragma unroll
        for (int mf = 0; mf < 4; mf++)
#pragma unroll
            for (int nf = 0; nf < 4; nf++)
                mma_f16(acc[mf][nf][0], acc[mf][nf][1], acc[mf][nf][2], acc[mf][nf][3],
                        ah[mf][0], ah[mf][1], ah[mf][2], ah[mf][3],
                        bf[nf][0], bf[nf][1]);
    }

#pragma unroll
    for (int mf = 0; mf < 4; mf++) {
        const int row = by * 128 + wm + mf * 16 + gi;
#pragma unroll
        for (int nf = 0; nf < 4; nf++) {
            const int col = bx * 128 + wn + nf * 8 + 2 * ti;
            const float bv0 = bias[col], bv1 = bias[col + 1];
            float2 v0, v1;
            v0.x = acc[mf][nf][0] + bv0; v0.y = acc[mf][nf][1] + bv1;
            v1.x = acc[mf][nf][2] + bv0; v1.y = acc[mf][nf][3] + bv1;
            *(float2*)(&Cc[(size_t)row * N + col])       = v0;
            *(float2*)(&Cc[(size_t)(row + 8) * N + col]) = v1;
        }
    }
}

// ---------------------------------------------------------------------------
// Combined K/V pre-convert: K -> fp16 [h][t][d] (passthrough),
// V -> fp16 transposed [h][d][t] (smem 64x64 transpose). One kernel.
// ---------------------------------------------------------------------------
__global__ __launch_bounds__(256) void k_cvtKV()
{
    __shared__ __half S[64][72];
    const int tid = threadIdx.x;
    const int t0  = blockIdx.x * 64;
    const int h   = blockIdx.y;
    const int tr  = tid >> 2;
    const int dp  = (tid & 3) << 4;

    // K rows: convert + direct store
    {
        const float* ksrc = g_qkv + (size_t)(t0 + tr) * F_DIM + C_DIM + h * 64 + dp;
        __half* kdst = g_k16 + ((size_t)h * T_DIM + t0 + tr) * 64 + dp;
        uint4 o0, o1;
        float4 a = *(const float4*)(ksrc);
        float4 b = *(const float4*)(ksrc + 4);
        o0.x = h2_as_u32(__floats2half2_rn(a.x, a.y));
        o0.y = h2_as_u32(__floats2half2_rn(a.z, a.w));
        o0.z = h2_as_u32(__floats2half2_rn(b.x, b.y));
        o0.w = h2_as_u32(__floats2half2_rn(b.z, b.w));
        a = *(const float4*)(ksrc + 8);
        b = *(const float4*)(ksrc + 12);
        o1.x = h2_as_u32(__floats2half2_rn(a.x, a.y));
        o1.y = h2_as_u32(__floats2half2_rn(a.z, a.w));
        o1.z = h2_as_u32(__floats2half2_rn(b.x, b.y));
        o1.w = h2_as_u32(__floats2half2_rn(b.z, b.w));
        *(uint4*)(kdst)     = o0;
        *(uint4*)(kdst + 8) = o1;
    }

    // V rows: convert into smem, then write transposed
    {
        const float* vsrc = g_qkv + (size_t)(t0 + tr) * F_DIM + 2 * C_DIM + h * 64 + dp;
#pragma unroll
        for (int e = 0; e < 4; e++) {
            float4 v = *(const float4*)(vsrc + 4 * e);
            __half2 p0 = __floats2half2_rn(v.x, v.y);
            __half2 p1 = __floats2half2_rn(v.z, v.w);
            *(__half2*)(&S[tr][dp + 4 * e])     = p0;
            *(__half2*)(&S[tr][dp + 4 * e + 2]) = p1;
        }
    }
    __syncthreads();
    {
        const int d  = tid >> 2;
        const int tp = (tid & 3) << 4;
        __half* dst = g_v16t + ((size_t)h * 64 + d) * T_DIM + t0 + tp;
#pragma unroll
        for (int e = 0; e < 8; e++) {
            __half2 v = __halves2half2(S[tp + 2 * e][d], S[tp + 2 * e + 1][d]);
            *(__half2*)(dst + 2 * e) = v;
        }
    }
}

// ---------------------------------------------------------------------------
// Causal flash attention, fp16 mma, CONCURRENT paired q-blocks
// (unchanged from round 15).
// ---------------------------------------------------------------------------
__global__ __launch_bounds__(256) void k_flash()
{
    __shared__ __align__(16) __half Ks[2][64][72];   // [buf][key][d]
    __shared__ __align__(16) __half Vt[2][64][72];   // [buf][d][key]

    const int x    = blockIdx.x;          // 0..31
    const int h    = blockIdx.y;
    const int tid  = threadIdx.x;
    const int wg   = tid >> 7;            // warpgroup 0/1
    const int wtid = tid & 127;
    const int w    = wtid >> 5;           // warp within group 0..3
    const int lane = tid & 31;
    const int gi   = lane >> 2;
    const int ti   = lane & 3;

    const int qb   = wg ? x : (63 - x);   // this warpgroup's q-block
    const int jmax = 63 - x;              // tiles to stream

    unsigned qa[4][4];
    {
        const float* q0 = g_qkv + (size_t)(qb * 64 + w * 16 + gi) * F_DIM + h * 64;
        const float* q1 = q0 + 8 * F_DIM;
#pragma unroll
        for (int kc = 0; kc < 4; kc++) {
            const int c0 = kc * 16 + 2 * ti;
            qa[kc][0] = h2_as_u32(__floats2half2_rn(q0[c0] * QSCALE,     q0[c0 + 1] * QSCALE));
            qa[kc][1] = h2_as_u32(__floats2half2_rn(q1[c0] * QSCALE,     q1[c0 + 1] * QSCALE));
            qa[kc][2] = h2_as_u32(__floats2half2_rn(q0[c0 + 8] * QSCALE, q0[c0 + 9] * QSCALE));
            qa[kc][3] = h2_as_u32(__floats2half2_rn(q1[c0 + 8] * QSCALE, q1[c0 + 9] * QSCALE));
        }
    }

    float o[8][4];
#pragma unroll
    for (int n = 0; n < 8; n++) { o[n][0] = o[n][1] = o[n][2] = o[n][3] = 0.f; }
    float m0 = -1e30f, m1 = -1e30f, l0 = 0.f, l1 = 0.f;

    const __half* kbase = g_k16 + (size_t)h * T_DIM * 64;
    const __half* vbase = g_v16t + (size_t)h * 64 * T_DIM;
    const int frow = tid >> 2;            // 0..63
    const int fcol = (tid & 3) << 4;      // 0,16,32,48

    auto produce = [&](int j, int buf) {
        const __half* ksrc = kbase + (size_t)(j * 64 + frow) * 64 + fcol;
        __half* kdst = &Ks[buf][frow][fcol];
        cp_async16(kdst,     ksrc);
        cp_async16(kdst + 8, ksrc + 8);
        const __half* vsrc = vbase + (size_t)frow * T_DIM + j * 64 + fcol;
        __half* vdst = &Vt[buf][frow][fcol];
        cp_async16(vdst,     vsrc);
        cp_async16(vdst + 8, vsrc + 8);
        asm volatile("cp.async.commit_group;" ::: "memory");
    };

    produce(0, 0);

    for (int j = 0; j <= jmax; j++) {
        asm volatile("cp.async.wait_group 0;" ::: "memory");
        __syncthreads();
        if (j < jmax) produce(j + 1, (j + 1) & 1);
        const int buf = j & 1;

        if (j <= qb) {
            float s[8][4];
#pragma unroll
            for (int n = 0; n < 8; n++) { s[n][0] = s[n][1] = s[n][2] = s[n][3] = 0.f; }
#pragma unroll
            for (int kc = 0; kc < 4; kc++) {
#pragma unroll
                for (int n = 0; n < 8; n++) {
                    unsigned b0 = *(const unsigned*)(&Ks[buf][n * 8 + gi][kc * 16 + 2 * ti]);
                    unsigned b1 = *(const unsigned*)(&Ks[buf][n * 8 + gi][kc * 16 + 2 * ti + 8]);
                    mma_f16(s[n][0], s[n][1], s[n][2], s[n][3],
                            qa[kc][0], qa[kc][1], qa[kc][2], qa[kc][3], b0, b1);
                }
            }

            if (j == qb) {
                const int r0l = w * 16 + gi;
                const int r1l = r0l + 8;
#pragma unroll
                for (int n = 0; n < 8; n++) {
                    const int col = n * 8 + 2 * ti;
                    if (col     > r0l) s[n][0] = -1e30f;
                    if (col + 1 > r0l) s[n][1] = -1e30f;
                    if (col     > r1l) s[n][2] = -1e30f;
                    if (col + 1 > r1l) s[n][3] = -1e30f;
                }
            }

            float rmax0 = -1e30f, rmax1 = -1e30f;
#pragma unroll
            for (int n = 0; n < 8; n++) {
                rmax0 = fmaxf(rmax0, fmaxf(s[n][0], s[n][1]));
                rmax1 = fmaxf(rmax1, fmaxf(s[n][2], s[n][3]));
            }
            rmax0 = fmaxf(rmax0, __shfl_xor_sync(0xffffffffu, rmax0, 1));
            rmax0 = fmaxf(rmax0, __shfl_xor_sync(0xffffffffu, rmax0, 2));
            rmax1 = fmaxf(rmax1, __shfl_xor_sync(0xffffffffu, rmax1, 1));
            rmax1 = fmaxf(rmax1, __shfl_xor_sync(0xffffffffu, rmax1, 2));

            const float mn0 = fmaxf(m0, rmax0);
            const float mn1 = fmaxf(m1, rmax1);
            const float corr0 = exp2f(m0 - mn0);
            const float corr1 = exp2f(m1 - mn1);
            m0 = mn0; m1 = mn1;

            unsigned ph[8][2];
            float sum0 = 0.f, sum1 = 0.f;
#pragma unroll
            for (int n = 0; n < 8; n++) {
                float p00 = exp2f(s[n][0] - mn0);
                float p01 = exp2f(s[n][1] - mn0);
                float p10 = exp2f(s[n][2] - mn1);
                float p11 = exp2f(s[n][3] - mn1);
                sum0 += p00 + p01;
                sum1 += p10 + p11;
                ph[n][0] = h2_as_u32(__floats2half2_rn(p00, p01));
                ph[n][1] = h2_as_u32(__floats2half2_rn(p10, p11));
            }
            sum0 += __shfl_xor_sync(0xffffffffu, sum0, 1);
            sum0 += __shfl_xor_sync(0xffffffffu, sum0, 2);
            sum1 += __shfl_xor_sync(0xffffffffu, sum1, 1);
            sum1 += __shfl_xor_sync(0xffffffffu, sum1, 2);
            l0 = l0 * corr0 + sum0;
            l1 = l1 * corr1 + sum1;

#pragma unroll
            for (int n = 0; n < 8; n++) {
                o[n][0] *= corr0; o[n][1] *= corr0;
                o[n][2] *= corr1; o[n][3] *= corr1;
            }

#pragma unroll
            for (int kc = 0; kc < 4; kc++) {
                unsigned a0 = ph[2 * kc][0];
                unsigned a1 = ph[2 * kc][1];
                unsigned a2 = ph[2 * kc + 1][0];
                unsigned a3 = ph[2 * kc + 1][1];
#pragma unroll
                for (int n = 0; n < 8; n++) {
                    unsigned b0 = *(const unsigned*)(&Vt[buf][n * 8 + gi][kc * 16 + 2 * ti]);
                    unsigned b1 = *(const unsigned*)(&Vt[buf][n * 8 + gi][kc * 16 + 2 * ti + 8]);
                    mma_f16(o[n][0], o[n][1], o[n][2], o[n][3], a0, a1, a2, a3, b0, b1);
                }
            }
        }
        __syncthreads();   // all warps done reading buf before next overwrite
    }

    const float inv0 = 1.f / l0;
    const float inv1 = 1.f / l1;
    const int row0 = qb * 64 + w * 16 + gi;
    float* y0 = g_y + (size_t)row0 * C_DIM + h * 64;
    float* y1 = y0 + 8 * C_DIM;
#pragma unroll
    for (int n = 0; n < 8; n++) {
        float2 v0, v1;
        v0.x = o[n][0] * inv0; v0.y = o[n][1] * inv0;
        v1.x = o[n][2] * inv1; v1.y = o[n][3] * inv1;
        *(float2*)(y0 + n * 8 + 2 * ti) = v0;
        *(float2*)(y1 + n * 8 + 2 * ti) = v1;
    }
}

// ---------------------------------------------------------------------------
// Launch: cvt(x,Wqkv) -> qkv GEMM -> cvt K/V -> flash -> cvt(y,Wproj) -> proj
// ---------------------------------------------------------------------------
extern "C" void kernel_launch(void* const* d_in, const int* in_sizes, int n_in,
                              void* d_out, int out_size)
{
    (void)in_sizes; (void)n_in; (void)out_size;
    const float* x      = (const float*)d_in[0];
    const float* W_qkv  = (const float*)d_in[2];
    const float* b_qkv  = (const float*)d_in[3];
    const float* W_proj = (const float*)d_in[4];
    const float* b_proj = (const float*)d_in[5];
    float* out = (float*)d_out;

    __half *ah, *bt;
    cudaGetSymbolAddress((void**)&ah, g_ah);
    cudaGetSymbolAddress((void**)&bt, g_bt);
    float *qkv_out, *y_in;
    cudaGetSymbolAddress((void**)&qkv_out, g_qkv);
    cudaGetSymbolAddress((void**)&y_in, g_y);

    // QKV GEMM operands + GEMM
    k_cvtA<<<T_DIM * C_DIM / 8 / 256, 256>>>(x, ah);
    dim3 gw1(F_DIM / 32, C_DIM / 32);
    k_cvtWt<<<gw1, 256>>>(W_qkv, bt, C_DIM, F_DIM);
    dim3 g1(F_DIM / 128, T_DIM / 128);   // (18, 32)
    k_gemm16<<<g1, 256>>>(ah, bt, b_qkv, qkv_out, F_DIM, C_DIM);

    // K/V fp16 pre-convert + attention
    dim3 gv(T_DIM / 64, H_DIM);          // (64, 12)
    k_cvtKV<<<gv, 256>>>();
    dim3 g2(T_DIM / 128, H_DIM);         // (32, 12)
    k_flash<<<g2, 256>>>();

    // Proj GEMM operands + GEMM
    k_cvtA<<<T_DIM * C_DIM / 8 / 256, 256>>>(y_in, ah);
    dim3 gw2(C_DIM / 32, C_DIM / 32);
    k_cvtWt<<<gw2, 256>>>(W_proj, bt, C_DIM, C_DIM);
    dim3 g3(C_DIM / 128, T_DIM / 128);   // (6, 32)
    k_gemm16<<<g3, 256>>>(ah, bt, b_proj, out, C_DIM, C_DIM);
}